// round 6
// baseline (speedup 1.0000x reference)
#include <cuda_runtime.h>
#include <cuda_bf16.h>
#include <mma.h>
#include <cstdint>

using namespace nvcuda;

#define NB 8
#define NT 4096
#define NA 64
#define DD 256
#define MTOK (NB*NT)

// ---------------- scratch (device globals; no allocations allowed) ----------
__device__ __nv_bfloat16 g_xb[MTOK*DD];              // x in bf16
__device__ __nv_bfloat16 g_Wfc2[DD*DD];              // W_fc2 bf16 [K,N]
__device__ float        g_qaf[NA*DD];                // q_agent fp32 (scale folded)
__device__ float        g_kaf[NA*DD];                // k_agent fp32 (scale folded)
__device__ __nv_bfloat16 g_qap[NA*DD];               // qa' = qa_s @ Wk^T, bf16
__device__ __nv_bfloat16 g_kat[NA*DD];               // (Wq @ ka_s^T)^T, bf16 [a,i]
__device__ float        g_dbias[NA];                 // bq . ka_s
__device__ float        g_Wvf[DD*DD];                // Wv @ Wfc1, fp32
__device__ float        g_bvf[DD];                   // bv@Wfc1 + bfc1
__device__ float        g_S1[NB*NA*NT];              // stage-1 logits
__device__ __nv_bfloat16 g_P1[NB*NA*NT];             // stage-1 probs
__device__ float        g_vap[NB*8*NA*DD];           // split-K partials of P1@x
__device__ __nv_bfloat16 g_va[NB*NA*DD];             // u@Wvf+bvf, bf16
__device__ __nv_bfloat16 g_mid[MTOK*DD];             // attn2 @ va, bf16

// ---------------- cp.async helpers ------------------------------------------
__device__ __forceinline__ uint32_t smem_u32(const void* p) {
    uint32_t a;
    asm("{ .reg .u64 t; cvta.to.shared.u64 t, %1; cvt.u32.u64 %0, t; }" : "=r"(a) : "l"(p));
    return a;
}
#define CPA16(s, g)  asm volatile("cp.async.cg.shared.global [%0], [%1], 16;" :: "r"(s), "l"(g))
#define CPA_COMMIT() asm volatile("cp.async.commit_group;" ::: "memory")
#define CPA_WAIT(n)  asm volatile("cp.async.wait_group %0;" :: "n"(n) : "memory")

// ---------------- input conversion (x, W_fc2 only) ---------------------------
__global__ void conv_inputs(const float* __restrict__ x,
                            const float* __restrict__ Wfc2) {
    int stride = gridDim.x * blockDim.x;
    int tid = blockIdx.x * blockDim.x + threadIdx.x;
    for (int i = tid; i < (MTOK*DD)/4; i += stride) {
        float4 v = *(const float4*)(x + i*4);
        __nv_bfloat16 t[4] = {__float2bfloat16(v.x), __float2bfloat16(v.y),
                              __float2bfloat16(v.z), __float2bfloat16(v.w)};
        *(uint2*)(g_xb + i*4) = *(uint2*)t;
    }
    for (int i = tid; i < DD*DD; i += stride)
        g_Wfc2[i] = __float2bfloat16(Wfc2[i]);
}

// ---------------- agent projection (fp32 out, scale folded) -----------------
__global__ void agent_proj(const float* __restrict__ agent,
                           const float* __restrict__ W,
                           const float* __restrict__ b) {
    __shared__ float arow[DD];
    int a = blockIdx.x;
    for (int i = threadIdx.x; i < DD; i += blockDim.x)
        arow[i] = agent[a*DD + i];
    __syncthreads();
    int o = threadIdx.x;  // 0..511
    float s = 0.f;
    #pragma unroll 8
    for (int d = 0; d < DD; d++)
        s += arow[d] * W[d*2*DD + o];
    s += b[o];
    s *= 0.0625f;  // 256^-0.5
    if (o < DD) g_qaf[a*DD + o]      = s;
    else        g_kaf[a*DD + (o-DD)] = s;
}

// ---------------- qa' = qa_s @ Wk^T  (Wk = W_qkv[:,256:512]) ----------------
__global__ void proj_qa(const float* __restrict__ Wqkv) {
    __shared__ float qa[DD];
    int a = blockIdx.x;
    for (int i = threadIdx.x; i < DD; i += 256) qa[i] = g_qaf[a*DD + i];
    __syncthreads();
    int i = threadIdx.x;  // output dim (x-dim)
    float s = 0.f;
    #pragma unroll 8
    for (int o = 0; o < DD; o++)
        s += qa[o] * Wqkv[i*3*DD + DD + o];
    g_qap[a*DD + i] = __float2bfloat16(s);
}

// ---------------- KaT = (Wq @ ka_s^T)^T  + dbias = bq.ka_s ------------------
__global__ void proj_ka(const float* __restrict__ Wqkv, const float* __restrict__ bqkv) {
    __shared__ float ka[DD];
    __shared__ float red[256];
    int a = blockIdx.x;
    for (int i = threadIdx.x; i < DD; i += 256) ka[i] = g_kaf[a*DD + i];
    __syncthreads();
    int i = threadIdx.x;
    float s = 0.f;
    #pragma unroll 8
    for (int o = 0; o < DD; o++)
        s += ka[o] * Wqkv[i*3*DD + o];
    g_kat[a*DD + i] = __float2bfloat16(s);
    // dbias[a] = sum_o bq[o]*ka[o]
    red[i] = bqkv[i] * ka[i];
    __syncthreads();
    for (int st = 128; st > 0; st >>= 1) {
        if (i < st) red[i] += red[i + st];
        __syncthreads();
    }
    if (i == 0) g_dbias[a] = red[0];
}

// ---------------- Wvf = Wv @ Wfc1, bvf = bv@Wfc1 + bfc1 ---------------------
__global__ void wvf_k(const float* __restrict__ Wqkv, const float* __restrict__ Wfc1,
                      const float* __restrict__ bqkv, const float* __restrict__ bfc1) {
    __shared__ float wv[DD];
    int i = blockIdx.x;
    for (int o = threadIdx.x; o < DD; o += 256) wv[o] = Wqkv[i*3*DD + 2*DD + o];
    __syncthreads();
    int j = threadIdx.x;
    float s = 0.f;
    #pragma unroll 8
    for (int o = 0; o < DD; o++)
        s += wv[o] * Wfc1[o*DD + j];
    g_Wvf[i*DD + j] = s;
    if (i == 0) {
        float t = bfc1[j];
        #pragma unroll 8
        for (int o = 0; o < DD; o++)
            t += bqkv[2*DD + o] * Wfc1[o*DD + j];
        g_bvf[j] = t;
    }
}

// ---------------- stage-1 logits: S1[b] = qa' @ x_b^T -----------------------
// (qa.bk term is row-constant -> cancels in softmax; omitted)
// tile 64x128, BK=32, 2-stage cp.async, one sync/iter, 8 warps (2x4)
__global__ void __launch_bounds__(256) gemm_s1() {
    __shared__ __nv_bfloat16 Qa[2][64][40];
    __shared__ __nv_bfloat16 Ks[2][128][40];
    __shared__ float epi[8][16][16];
    uint32_t sQ = smem_u32(&Qa[0][0][0]);
    uint32_t sK = smem_u32(&Ks[0][0][0]);

    int b = blockIdx.y;
    int col0 = blockIdx.x * 128;
    int tid = threadIdx.x;
    int w = tid >> 5, lane = tid & 31;
    int wm = w >> 2, wn = w & 3;

    wmma::fragment<wmma::accumulator,16,16,16,float> acc[2][2];
    #pragma unroll
    for (int i = 0; i < 2; i++)
        #pragma unroll
        for (int j = 0; j < 2; j++) wmma::fill_fragment(acc[i][j], 0.f);

    #define S1_STAGE(kc, bb) {                                                     \
        {   int ar = tid >> 2, ac = (tid & 3) * 8;                                 \
            CPA16(sQ + (uint32_t)(bb)*5120u + (uint32_t)ar*80u + (uint32_t)ac*2u,  \
                  g_qap + (size_t)ar*DD + (kc) + ac); }                            \
        _Pragma("unroll")                                                          \
        for (int r = 0; r < 2; r++) {                                              \
            int idx = tid + r*256;                                                 \
            int kr = idx >> 2, kcc = (idx & 3) * 8;                                \
            CPA16(sK + (uint32_t)(bb)*10240u + (uint32_t)kr*80u + (uint32_t)kcc*2u,\
                  g_xb + (size_t)(b*NT + col0 + kr)*DD + (kc) + kcc);              \
        }                                                                          \
        CPA_COMMIT(); }

    S1_STAGE(0, 0);
    for (int s = 0; s < 8; s++) {
        CPA_WAIT(0);
        __syncthreads();
        if (s < 7) S1_STAGE((s+1)*32, (s+1)&1);
        int bb = s & 1;
        #pragma unroll
        for (int kk = 0; kk < 2; kk++) {
            wmma::fragment<wmma::matrix_a,16,16,16,__nv_bfloat16,wmma::row_major> af[2];
            wmma::fragment<wmma::matrix_b,16,16,16,__nv_bfloat16,wmma::col_major> bf[2];
            #pragma unroll
            for (int i = 0; i < 2; i++)
                wmma::load_matrix_sync(af[i], &Qa[bb][wm*32 + i*16][kk*16], 40);
            #pragma unroll
            for (int j = 0; j < 2; j++)
                wmma::load_matrix_sync(bf[j], &Ks[bb][wn*32 + j*16][kk*16], 40);
            #pragma unroll
            for (int i = 0; i < 2; i++)
                #pragma unroll
                for (int j = 0; j < 2; j++)
                    wmma::mma_sync(acc[i][j], af[i], bf[j], acc[i][j]);
        }
    }
    #undef S1_STAGE

    float* outb = g_S1 + (size_t)b*NA*NT;
    #pragma unroll
    for (int i = 0; i < 2; i++)
        #pragma unroll
        for (int j = 0; j < 2; j++) {
            wmma::store_matrix_sync(&epi[w][0][0], acc[i][j], 16, wmma::mem_row_major);
            __syncwarp();
            #pragma unroll
            for (int e = 0; e < 2; e++) {
                int idx2 = lane + e*32;
                int r = idx2 >> 2, c4 = (idx2 & 3) * 4;
                int ga = wm*32 + i*16 + r;
                int gt = col0 + wn*32 + j*16 + c4;
                *(float4*)(outb + (size_t)ga*NT + gt) = *(float4*)(&epi[w][r][c4]);
            }
            __syncwarp();
        }
}

// ---------------- stage-1 softmax over N=4096 (smem row cache) --------------
__global__ void softmax1() {
    __shared__ float rowc[NT];
    __shared__ float red[8];
    int row = blockIdx.x;
    const float* s = g_S1 + (size_t)row*NT;
    __nv_bfloat16* p = g_P1 + (size_t)row*NT;
    int t = threadIdx.x;

    float m = -1e30f;
    for (int i = t; i < NT/4; i += 256) {
        float4 v = *(const float4*)(s + i*4);
        *(float4*)(rowc + i*4) = v;
        m = fmaxf(fmaxf(m, fmaxf(v.x, v.y)), fmaxf(v.z, v.w));
    }
    #pragma unroll
    for (int o = 16; o; o >>= 1) m = fmaxf(m, __shfl_xor_sync(0xffffffffu, m, o));
    if ((t & 31) == 0) red[t >> 5] = m;
    __syncthreads();
    float gm = red[0];
    #pragma unroll
    for (int i = 1; i < 8; i++) gm = fmaxf(gm, red[i]);
    __syncthreads();

    float sum = 0.f;
    for (int i = t; i < NT; i += 256) sum += __expf(rowc[i] - gm);
    #pragma unroll
    for (int o = 16; o; o >>= 1) sum += __shfl_xor_sync(0xffffffffu, sum, o);
    if ((t & 31) == 0) red[t >> 5] = sum;
    __syncthreads();
    float gs = 0.f;
    #pragma unroll
    for (int i = 0; i < 8; i++) gs += red[i];
    float inv = 1.f / gs;
    for (int i = t; i < NT/4; i += 256) {
        float4 v = *(const float4*)(rowc + i*4);
        __nv_bfloat16 t4[4] = {
            __float2bfloat16(__expf(v.x - gm) * inv),
            __float2bfloat16(__expf(v.y - gm) * inv),
            __float2bfloat16(__expf(v.z - gm) * inv),
            __float2bfloat16(__expf(v.w - gm) * inv)};
        *(uint2*)(p + i*4) = *(uint2*)t4;
    }
}

// ---------------- u partials: split-K over tokens (u = P1 @ x) ---------------
// grid (8 splits, 8 batches), 2-stage cp.async, one sync/iter
__global__ void __launch_bounds__(256) gemm_va0() {
    __shared__ __align__(16) char smva[44032];
    __nv_bfloat16 (*Ps)[64][40]  = ( __nv_bfloat16(*)[64][40])  smva;          // 2x5120
    __nv_bfloat16 (*Vs)[32][264] = ( __nv_bfloat16(*)[32][264])(smva + 10240); // 2x16896
    float (*epi)[16][16]         = ( float(*)[16][16])          smva;          // reuse Ps
    uint32_t sP = smem_u32(smva), sV = sP + 10240u;

    int split = blockIdx.x, b = blockIdx.y;
    int tok0 = split * 512;
    int tid = threadIdx.x;
    int w = tid >> 5, lane = tid & 31;
    int wm = w >> 2, wn = w & 3;

    wmma::fragment<wmma::accumulator,16,16,16,float> acc[2][4];
    #pragma unroll
    for (int i = 0; i < 2; i++)
        #pragma unroll
        for (int j = 0; j < 4; j++) wmma::fill_fragment(acc[i][j], 0.f);

    #define VA_STAGE(kc, bb) {                                                     \
        {   int pr = tid >> 2, pc = (tid & 3) * 8;                                 \
            CPA16(sP + (uint32_t)(bb)*5120u + (uint32_t)pr*80u + (uint32_t)pc*2u,  \
                  g_P1 + (size_t)b*NA*NT + (size_t)pr*NT + tok0 + (kc) + pc); }    \
        _Pragma("unroll")                                                          \
        for (int r = 0; r < 4; r++) {                                              \
            int idx = tid + r*256;                                                 \
            int vr = idx >> 5, vc = (idx & 31) * 8;                                \
            CPA16(sV + (uint32_t)(bb)*16896u + (uint32_t)vr*528u + (uint32_t)vc*2u,\
                  g_xb + (size_t)(b*NT + tok0 + (kc) + vr)*DD + vc);               \
        }                                                                          \
        CPA_COMMIT(); }

    VA_STAGE(0, 0);
    for (int s = 0; s < 16; s++) {
        CPA_WAIT(0);
        __syncthreads();
        if (s < 15) VA_STAGE((s+1)*32, (s+1)&1);
        int bb = s & 1;
        #pragma unroll
        for (int kk = 0; kk < 2; kk++) {
            wmma::fragment<wmma::matrix_a,16,16,16,__nv_bfloat16,wmma::row_major> af[2];
            wmma::fragment<wmma::matrix_b,16,16,16,__nv_bfloat16,wmma::row_major> bf[4];
            #pragma unroll
            for (int i = 0; i < 2; i++)
                wmma::load_matrix_sync(af[i], &Ps[bb][wm*32 + i*16][kk*16], 40);
            #pragma unroll
            for (int j = 0; j < 4; j++)
                wmma::load_matrix_sync(bf[j], &Vs[bb][kk*16][wn*64 + j*16], 264);
            #pragma unroll
            for (int i = 0; i < 2; i++)
                #pragma unroll
                for (int j = 0; j < 4; j++)
                    wmma::mma_sync(acc[i][j], af[i], bf[j], acc[i][j]);
        }
    }
    #undef VA_STAGE
    __syncthreads();

    float* outb = g_vap + (size_t)(b*8 + split)*NA*DD;
    #pragma unroll
    for (int i = 0; i < 2; i++)
        #pragma unroll
        for (int j = 0; j < 4; j++) {
            wmma::store_matrix_sync(&epi[w][0][0], acc[i][j], 16, wmma::mem_row_major);
            __syncwarp();
            #pragma unroll
            for (int e = 0; e < 2; e++) {
                int idx2 = lane + e*32;
                int r = idx2 >> 2, c4 = (idx2 & 3) * 4;
                int ga = wm*32 + i*16 + r;
                int gd = wn*64 + j*16 + c4;
                *(float4*)(outb + (size_t)ga*DD + gd) = *(float4*)(&epi[w][r][c4]);
            }
            __syncwarp();
        }
}

// ---------------- fc1: sum partials, then va = u @ Wvf + bvf ----------------
__global__ void fc1k() {
    __shared__ float r0[DD];
    int row = blockIdx.x;  // b*NA + a
    int b = row >> 6, a = row & 63;
    int i = threadIdx.x;
    float acc = 0.f;
    #pragma unroll
    for (int sp = 0; sp < 8; sp++)
        acc += g_vap[(size_t)(b*8 + sp)*NA*DD + (size_t)a*DD + i];
    r0[i] = acc;
    __syncthreads();
    int o = threadIdx.x;
    float s = g_bvf[o];
    #pragma unroll 8
    for (int d = 0; d < DD; d++) s += r0[d] * g_Wvf[d*DD + o];
    g_va[(size_t)row*DD + o] = __float2bfloat16(s);
}

// ---------------- stage 2: logits(x@Ka') + dbias -> softmax -> @ va ---------
// per block: 128 tokens of one batch. Dynamic smem 99328B, cp.async staging.
__global__ void __launch_bounds__(256) stage2() {
    extern __shared__ __align__(16) char sm2[];
    __nv_bfloat16 (*Qs)[128][40] = ( __nv_bfloat16(*)[128][40]) sm2;             // 20480
    __nv_bfloat16 (*Ka)[64][40]  = ( __nv_bfloat16(*)[64][40]) (sm2 + 20480);    // 10240
    float* logits                = ( float*)                   (sm2 + 30720);    // 34816
    __nv_bfloat16 (*Vs)[264]     = ( __nv_bfloat16(*)[264])    (sm2 + 65536);    // 33792
    __nv_bfloat16 (*Pm)[72]      = ( __nv_bfloat16(*)[72])     sm2;              // reuse Qs
    float (*epi)[16][16]         = ( float(*)[16][16])         (sm2 + 20480);    // reuse Ka
    __shared__ float dbs[NA];
    uint32_t sQ = smem_u32(sm2), sKa = sQ + 20480u, sV = sQ + 65536u;

    int b = blockIdx.y, t0 = blockIdx.x * 128;
    int tid = threadIdx.x;
    int w = tid >> 5, lane = tid & 31;

    if (tid < NA) dbs[tid] = g_dbias[tid];

    // async prefetch va tile [64,256] into Vs
    #pragma unroll
    for (int r = 0; r < 8; r++) {
        int idx = tid + r*256;
        int vr = idx >> 5, vc = (idx & 31) * 8;
        CPA16(sV + (uint32_t)vr*528u + (uint32_t)vc*2u,
              g_va + (size_t)(b*NA + vr)*DD + vc);
    }
    CPA_COMMIT();

    // --- phase A: logits[128,64] = x_tile @ KaT^T, warps 4x2, warp 32x32 ---
    {
        int wm = w >> 1, wn = w & 1;
        wmma::fragment<wmma::accumulator,16,16,16,float> acc[2][2];
        #pragma unroll
        for (int i = 0; i < 2; i++)
            #pragma unroll
            for (int j = 0; j < 2; j++) wmma::fill_fragment(acc[i][j], 0.f);

        #define S2_STAGE(kc, bb) {                                                 \
            _Pragma("unroll")                                                      \
            for (int r = 0; r < 2; r++) {                                          \
                int idx = tid + r*256;                                             \
                int qr = idx >> 2, qc = (idx & 3) * 8;                             \
                CPA16(sQ + (uint32_t)(bb)*10240u + (uint32_t)qr*80u + (uint32_t)qc*2u, \
                      g_xb + (size_t)(b*NT + t0 + qr)*DD + (kc) + qc);             \
            }                                                                      \
            {   int ar = tid >> 2, ac = (tid & 3) * 8;                             \
                CPA16(sKa + (uint32_t)(bb)*5120u + (uint32_t)ar*80u + (uint32_t)ac*2u, \
                      g_kat + (size_t)ar*DD + (kc) + ac); }                        \
            CPA_COMMIT(); }

        S2_STAGE(0, 0);
        for (int s = 0; s < 8; s++) {
            CPA_WAIT(0);
            __syncthreads();
            if (s < 7) S2_STAGE((s+1)*32, (s+1)&1);
            int bb = s & 1;
            #pragma unroll
            for (int kk = 0; kk < 2; kk++) {
                wmma::fragment<wmma::matrix_a,16,16,16,__nv_bfloat16,wmma::row_major> af[2];
                wmma::fragment<wmma::matrix_b,16,16,16,__nv_bfloat16,wmma::col_major> bf[2];
                #pragma unroll
                for (int i = 0; i < 2; i++)
                    wmma::load_matrix_sync(af[i], &Qs[bb][wm*32 + i*16][kk*16], 40);
                #pragma unroll
                for (int j = 0; j < 2; j++)
                    wmma::load_matrix_sync(bf[j], &Ka[bb][wn*32 + j*16][kk*16], 40);
                #pragma unroll
                for (int i = 0; i < 2; i++)
                    #pragma unroll
                    for (int j = 0; j < 2; j++)
                        wmma::mma_sync(acc[i][j], af[i], bf[j], acc[i][j]);
            }
        }
        #undef S2_STAGE
        __syncthreads();
        #pragma unroll
        for (int i = 0; i < 2; i++)
            #pragma unroll
            for (int j = 0; j < 2; j++)
                wmma::store_matrix_sync(logits + (wm*32 + i*16)*68 + wn*32 + j*16,
                                        acc[i][j], 68, wmma::mem_row_major);
    }
    __syncthreads();

    // --- phase B: per-row softmax over 64 agents (+dbias) -> Pm ---
    if (tid < 128) {
        const float* lr = logits + tid*68;
        float lv[64];
        #pragma unroll 8
        for (int c = 0; c < 64; c++) lv[c] = lr[c] + dbs[c];
        float m = -1e30f;
        #pragma unroll 8
        for (int c = 0; c < 64; c++) m = fmaxf(m, lv[c]);
        float sum = 0.f;
        #pragma unroll 8
        for (int c = 0; c < 64; c++) sum += __expf(lv[c] - m);
        float inv = 1.f / sum;
        #pragma unroll 8
        for (int c = 0; c < 64; c++)
            Pm[tid][c] = __float2bfloat16(__expf(lv[c] - m) * inv);
    }
    __syncthreads();

    // --- phase C: mid[128,256] = Pm[128,64] @ Vs[64,256]; two N passes ---
    {
        int wm = w >> 1, wn = w & 1;
        for (int nc = 0; nc < 2; nc++) {
            wmma::fragment<wmma::accumulator,16,16,16,float> acc[2][4];
            #pragma unroll
            for (int i = 0; i < 2; i++)
                #pragma unroll
                for (int j = 0; j < 4; j++) wmma::fill_fragment(acc[i][j], 0.f);
            #pragma unroll
            for (int kk = 0; kk < 4; kk++) {
                wmma::fragment<wmma::matrix_a,16,16,16,__nv_bfloat16,wmma::row_major> af[2];
                wmma::fragment<wmma::matrix_b,16,16,16,__nv_bfloat16,wmma::row_major> bf[4];
                #pragma unroll
                for (int i = 0; i < 2; i++)
                    wmma::load_matrix_sync(af[i], &Pm[wm*32 + i*16][kk*16], 72);
                #pragma unroll
                for (int j = 0; j < 4; j++)
                    wmma::load_matrix_sync(bf[j], &Vs[kk*16][nc*128 + wn*64 + j*16], 264);
                #pragma unroll
                for (int i = 0; i < 2; i++)
                    #pragma unroll
                    for (int j = 0; j < 4; j++)
                        wmma::mma_sync(acc[i][j], af[i], bf[j], acc[i][j]);
            }
            int r = lane >> 1, c8 = (lane & 1) * 8;
            #pragma unroll
            for (int i = 0; i < 2; i++)
                #pragma unroll
                for (int j = 0; j < 4; j++) {
                    wmma::store_matrix_sync(&epi[w][0][0], acc[i][j], 16, wmma::mem_row_major);
                    __syncwarp();
                    int grow = t0 + wm*32 + i*16 + r;
                    int gcol = nc*128 + wn*64 + j*16 + c8;
                    __nv_bfloat16 tmp[8];
                    #pragma unroll
                    for (int e = 0; e < 8; e++)
                        tmp[e] = __float2bfloat16(epi[w][r][c8+e]);
                    *(uint4*)(g_mid + (size_t)(b*NT + grow)*DD + gcol) = *(uint4*)tmp;
                    __syncwarp();
                }
        }
    }
}

// ---------------- fc2 + bias + residual -> out ------------------------------
// tile 128x128, BK=64, 2-stage, 4 warps (2x2), warp 64x64, one sync/iter
__global__ void __launch_bounds__(128) gemm_fc2(const float* __restrict__ bias,
                                                const float* __restrict__ x,
                                                float* __restrict__ out) {
    extern __shared__ __align__(16) char smf[];
    __nv_bfloat16 (*As)[128][72] = (__nv_bfloat16(*)[128][72]) smf;
    __nv_bfloat16 (*Bs)[64][136] = (__nv_bfloat16(*)[64][136])(smf + 36864);
    float (*epi)[16][16]         = (float(*)[16][16])          smf;
    uint32_t sA = smem_u32(smf), sB = sA + 36864u;

    int tid = threadIdx.x;
    int w = tid >> 5, lane = tid & 31;
    int wm = w >> 1, wn = w & 1;
    int row0 = blockIdx.y * 128, col0 = blockIdx.x * 128;

    wmma::fragment<wmma::accumulator,16,16,16,float> acc[4][4];
    #pragma unroll
    for (int i = 0; i < 4; i++)
        #pragma unroll
        for (int j = 0; j < 4; j++) wmma::fill_fragment(acc[i][j], 0.f);

    #define FC2_STAGE(kc, bb) {                                                    \
        _Pragma("unroll")                                                          \
        for (int r = 0; r < 8; r++) {                                              \
            int idx = tid + r*128;                                                 \
            int ar = idx >> 3, ac = (idx & 7) * 8;                                 \
            CPA16(sA + (uint32_t)(bb)*18432u + (uint32_t)ar*144u + (uint32_t)ac*2u,\
                  g_mid + (size_t)(row0+ar)*DD + (kc) + ac);                       \
        }                                                                          \
        _Pragma("unroll")                                                          \
        for (int r = 0; r < 8; r++) {                                              \
            int idx = tid + r*128;                                                 \
            int br = idx >> 4, bc = (idx & 15) * 8;                                \
            CPA16(sB + (uint32_t)(bb)*17408u + (uint32_t)br*272u + (uint32_t)bc*2u,\
                  g_Wfc2 + (size_t)((kc)+br)*DD + col0 + bc);                      \
        }                                                                          \
        CPA_COMMIT(); }

    FC2_STAGE(0, 0);
    for (int s = 0; s < 4; s++) {
        CPA_WAIT(0);
        __syncthreads();
        if (s < 3) FC2_STAGE((s+1)*64, (s+1)&1);
        int bb = s & 1;
        #pragma unroll
        for (int k4 = 0; k4 < 4; k4++) {
            wmma::fragment<wmma::matrix_a,16,16,16,__nv_bfloat16,wmma::row_major> af[4];
            wmma::fragment<wmma::matrix_b,16,16,16,__nv_bfloat16,wmma::row_major> bf[4];
            #pragma unroll
            for (int i = 0; i < 4; i++)
                wmma::load_matrix_sync(af[i], &As[bb][wm*64 + i*16][k4*16], 72);
            #pragma unroll
            for (int j = 0; j < 4; j++)
                wmma::load_matrix_sync(bf[j], &Bs[bb][k4*16][wn*64 + j*16], 136);
            #pragma unroll
            for (int i = 0; i < 4; i++)
                #pragma unroll
                for (int j = 0; j < 4; j++)
                    wmma::mma_sync(acc[i][j], af[i], bf[j], acc[i][j]);
        }
    }
    #undef FC2_STAGE
    __syncthreads();

    int r = lane >> 1, c8 = (lane & 1) * 8;
    #pragma unroll
    for (int i = 0; i < 4; i++)
        #pragma unroll
        for (int j = 0; j < 4; j++) {
            wmma::store_matrix_sync(&epi[w][0][0], acc[i][j], 16, wmma::mem_row_major);
            __syncwarp();
            int gr = row0 + wm*64 + i*16 + r;
            int gc = col0 + wn*64 + j*16 + c8;
            size_t gi = (size_t)gr*DD + gc;
            float o0[4], o1[4];
            #pragma unroll
            for (int e = 0; e < 4; e++) o0[e] = epi[w][r][c8+e]   + bias[gc+e]   + x[gi+e];
            #pragma unroll
            for (int e = 0; e < 4; e++) o1[e] = epi[w][r][c8+4+e] + bias[gc+4+e] + x[gi+4+e];
            *(float4*)(out + gi)     = *(float4*)o0;
            *(float4*)(out + gi + 4) = *(float4*)o1;
            __syncwarp();
        }
}

// ---------------- launcher ---------------------------------------------------
#define BIG_SMEM 71680

extern "C" void kernel_launch(void* const* d_in, const int* in_sizes, int n_in,
                              void* d_out, int out_size) {
    const float* agent = (const float*)d_in[0];
    const float* x     = (const float*)d_in[1];
    const float* Wqkv  = (const float*)d_in[2];
    const float* bqkv  = (const float*)d_in[3];
    const float* Wag   = (const float*)d_in[4];
    const float* bag   = (const float*)d_in[5];
    const float* Wfc1  = (const float*)d_in[6];
    const float* bfc1  = (const float*)d_in[7];
    const float* Wfc2  = (const float*)d_in[8];
    const float* bfc2  = (const float*)d_in[9];
    float* out = (float*)d_out;

    cudaFuncSetAttribute(stage2,   cudaFuncAttributeMaxDynamicSharedMemorySize, 99328);
    cudaFuncSetAttribute(gemm_fc2, cudaFuncAttributeMaxDynamicSharedMemorySize, BIG_SMEM);

    conv_inputs<<<2048, 256>>>(x, Wfc2);
    agent_proj<<<64, 512>>>(agent, Wag, bag);
    proj_qa<<<64, 256>>>(Wqkv);
    proj_ka<<<64, 256>>>(Wqkv, bqkv);
    wvf_k<<<256, 256>>>(Wqkv, Wfc1, bqkv, bfc1);
    gemm_s1<<<dim3(32, 8), 256>>>();
    softmax1<<<512, 256>>>();
    gemm_va0<<<dim3(8, 8), 256>>>();
    fc1k<<<512, 256>>>();
    stage2<<<dim3(32, 8), 256, 99328>>>();
    gemm_fc2<<<dim3(2, 256), 128, BIG_SMEM>>>(bfc2, x, out);
}

// round 7
// speedup vs baseline: 1.2216x; 1.2216x over previous
#include <cuda_runtime.h>
#include <cuda_bf16.h>
#include <mma.h>
#include <cstdint>

using namespace nvcuda;

#define NB 8
#define NT 4096
#define NA 64
#define DD 256
#define MTOK (NB*NT)
#define W3 (3*DD)

// ---------------- scratch (device globals; no allocations allowed) ----------
__device__ __nv_bfloat16 g_xb[MTOK*DD];              // x in bf16
__device__ __nv_bfloat16 g_Wfc2[DD*DD];              // W_fc2 bf16 [K,N]
__device__ __nv_bfloat16 g_Wqkvb[DD*W3];             // W_qkv bf16 [K, 3N]
__device__ __nv_bfloat16 g_Wfc1b[DD*DD];             // W_fc1 bf16 [K,N]
__device__ __nv_bfloat16 g_qasb[NA*DD];              // qa_s bf16 (scale folded)
__device__ __nv_bfloat16 g_kasb[NA*DD];              // ka_s bf16 (scale folded)
__device__ float        g_kaf[NA*DD];                // ka_s fp32 (for dbias)
__device__ __nv_bfloat16 g_qap[NA*DD];               // qa' = qa_s @ Wk^T, bf16
__device__ __nv_bfloat16 g_kat[NA*DD];               // Ka' [a,i] bf16
__device__ float        g_dbias[NA];                 // bq . ka_s
__device__ float        g_Wvf[DD*DD];                // Wv @ Wfc1, fp32
__device__ float        g_bvf[DD];                   // bv@Wfc1 + bfc1
__device__ float        g_S1[NB*NA*NT];              // stage-1 logits
__device__ __nv_bfloat16 g_P1[NB*NA*NT];             // stage-1 probs
__device__ float        g_vap[NB*8*NA*DD];           // split-K partials of P1@x
__device__ __nv_bfloat16 g_va[NB*NA*DD];             // u@Wvf+bvf, bf16
__device__ __nv_bfloat16 g_mid[MTOK*DD];             // attn2 @ va, bf16

// ---------------- cp.async helpers ------------------------------------------
__device__ __forceinline__ uint32_t smem_u32(const void* p) {
    uint32_t a;
    asm("{ .reg .u64 t; cvta.to.shared.u64 t, %1; cvt.u32.u64 %0, t; }" : "=r"(a) : "l"(p));
    return a;
}
#define CPA16(s, g)  asm volatile("cp.async.cg.shared.global [%0], [%1], 16;" :: "r"(s), "l"(g))
#define CPA_COMMIT() asm volatile("cp.async.commit_group;" ::: "memory")
#define CPA_WAIT(n)  asm volatile("cp.async.wait_group %0;" :: "n"(n) : "memory")

// ---------------- input conversion (x, W_fc2, W_qkv, W_fc1) -----------------
__global__ void conv_inputs(const float* __restrict__ x,
                            const float* __restrict__ Wfc2,
                            const float* __restrict__ Wqkv,
                            const float* __restrict__ Wfc1) {
    int stride = gridDim.x * blockDim.x;
    int tid = blockIdx.x * blockDim.x + threadIdx.x;
    for (int i = tid; i < (MTOK*DD)/4; i += stride) {
        float4 v = *(const float4*)(x + i*4);
        __nv_bfloat16 t[4] = {__float2bfloat16(v.x), __float2bfloat16(v.y),
                              __float2bfloat16(v.z), __float2bfloat16(v.w)};
        *(uint2*)(g_xb + i*4) = *(uint2*)t;
    }
    for (int i = tid; i < DD*DD; i += stride)
        g_Wfc2[i] = __float2bfloat16(Wfc2[i]);
    for (int i = tid; i < DD*W3; i += stride)
        g_Wqkvb[i] = __float2bfloat16(Wqkv[i]);
    for (int i = tid; i < DD*DD; i += stride)
        g_Wfc1b[i] = __float2bfloat16(Wfc1[i]);
}

// ---------------- agent projection (scale folded) ---------------------------
__global__ void agent_proj(const float* __restrict__ agent,
                           const float* __restrict__ W,
                           const float* __restrict__ b) {
    __shared__ float arow[DD];
    int a = blockIdx.x;
    for (int i = threadIdx.x; i < DD; i += blockDim.x)
        arow[i] = agent[a*DD + i];
    __syncthreads();
    int o = threadIdx.x;  // 0..511
    float s = 0.f;
    #pragma unroll 8
    for (int d = 0; d < DD; d++)
        s += arow[d] * W[d*2*DD + o];
    s += b[o];
    s *= 0.0625f;  // 256^-0.5
    if (o < DD) {
        g_qasb[a*DD + o] = __float2bfloat16(s);
    } else {
        g_kasb[a*DD + (o-DD)] = __float2bfloat16(s);
        g_kaf [a*DD + (o-DD)] = s;
    }
}

// ---------------- proj_agents (WMMA): qa' and Ka' ----------------------------
// grid (4, 2): x = 64-wide i-tile, y = sel (0: qa'=qa_s@Wk^T, 1: Ka'=ka_s@Wq^T)
// block 128 = 4 warps; each warp: M=64 x N=16
__global__ void __launch_bounds__(128) proj_agents() {
    int sel = blockIdx.y;
    int i0 = blockIdx.x * 64;
    const __nv_bfloat16* A = sel ? g_kasb : g_qasb;             // [64,256] row-major
    const __nv_bfloat16* Bb = g_Wqkvb + (sel ? 0 : DD);          // col offset in W3-wide
    __nv_bfloat16* C = sel ? g_kat : g_qap;
    int w = threadIdx.x >> 5;
    int icol = i0 + w*16;

    wmma::fragment<wmma::accumulator,16,16,16,float> acc[4];
    #pragma unroll
    for (int i = 0; i < 4; i++) wmma::fill_fragment(acc[i], 0.f);

    for (int kk = 0; kk < DD; kk += 16) {
        wmma::fragment<wmma::matrix_a,16,16,16,__nv_bfloat16,wmma::row_major> af[4];
        wmma::fragment<wmma::matrix_b,16,16,16,__nv_bfloat16,wmma::col_major> bf;
        #pragma unroll
        for (int i = 0; i < 4; i++)
            wmma::load_matrix_sync(af[i], A + (size_t)(i*16)*DD + kk, DD);
        // B(j,i) = W[i*W3 + off + j] -> col_major, ld = W3
        wmma::load_matrix_sync(bf, Bb + (size_t)icol*W3 + kk, W3);
        #pragma unroll
        for (int i = 0; i < 4; i++)
            wmma::mma_sync(acc[i], af[i], bf, acc[i]);
    }
    __shared__ float epi[4][16][16];
    int lane = threadIdx.x & 31;
    #pragma unroll
    for (int i = 0; i < 4; i++) {
        wmma::store_matrix_sync(&epi[w][0][0], acc[i], 16, wmma::mem_row_major);
        __syncwarp();
        if (lane < 16) {
            int a = i*16 + lane;
            __nv_bfloat16 t8[8];
            #pragma unroll
            for (int g = 0; g < 2; g++) {
                #pragma unroll
                for (int e = 0; e < 8; e++)
                    t8[e] = __float2bfloat16(epi[w][lane][g*8+e]);
                *(uint4*)(C + (size_t)a*DD + icol + g*8) = *(uint4*)t8;
            }
        }
        __syncwarp();
    }
}

// ---------------- Wvf = Wv @ Wfc1 (WMMA, fp32 out) --------------------------
// grid (2,2), block 256 = 8 warps (2x4), warp 64x32
__global__ void __launch_bounds__(256) wvf_wmma() {
    int row0 = blockIdx.y * 128, col0 = blockIdx.x * 128;
    int w = threadIdx.x >> 5;
    int wm = w >> 2, wn = w & 3;

    wmma::fragment<wmma::accumulator,16,16,16,float> acc[4][2];
    #pragma unroll
    for (int i = 0; i < 4; i++)
        #pragma unroll
        for (int j = 0; j < 2; j++) wmma::fill_fragment(acc[i][j], 0.f);

    for (int kk = 0; kk < DD; kk += 16) {
        wmma::fragment<wmma::matrix_a,16,16,16,__nv_bfloat16,wmma::row_major> af[4];
        wmma::fragment<wmma::matrix_b,16,16,16,__nv_bfloat16,wmma::row_major> bf[2];
        #pragma unroll
        for (int i = 0; i < 4; i++)
            wmma::load_matrix_sync(af[i], g_Wqkvb + (size_t)(row0 + wm*64 + i*16)*W3 + 2*DD + kk, W3);
        #pragma unroll
        for (int j = 0; j < 2; j++)
            wmma::load_matrix_sync(bf[j], g_Wfc1b + (size_t)kk*DD + col0 + wn*32 + j*16, DD);
        #pragma unroll
        for (int i = 0; i < 4; i++)
            #pragma unroll
            for (int j = 0; j < 2; j++)
                wmma::mma_sync(acc[i][j], af[i], bf[j], acc[i][j]);
    }
    #pragma unroll
    for (int i = 0; i < 4; i++)
        #pragma unroll
        for (int j = 0; j < 2; j++)
            wmma::store_matrix_sync(g_Wvf + (size_t)(row0 + wm*64 + i*16)*DD + col0 + wn*32 + j*16,
                                    acc[i][j], DD, wmma::mem_row_major);
}

// ---------------- dbias[a] = bq . ka_s ; bvf = bv@Wfc1 + bfc1 ---------------
__global__ void dbias_k(const float* __restrict__ bqkv) {
    __shared__ float red[256];
    int a = blockIdx.x, i = threadIdx.x;
    red[i] = bqkv[i] * g_kaf[a*DD + i];
    __syncthreads();
    for (int st = 128; st > 0; st >>= 1) {
        if (i < st) red[i] += red[i + st];
        __syncthreads();
    }
    if (i == 0) g_dbias[a] = red[0];
}
__global__ void bvf_k(const float* __restrict__ Wfc1,
                      const float* __restrict__ bqkv, const float* __restrict__ bfc1) {
    int j = threadIdx.x;
    float t = bfc1[j];
    #pragma unroll 8
    for (int o = 0; o < DD; o++)
        t += bqkv[2*DD + o] * Wfc1[o*DD + j];
    g_bvf[j] = t;
}

// ---------------- stage-1 logits: S1[b] = qa' @ x_b^T -----------------------
// tile 64x128, BK=32, 2-stage cp.async, one sync/iter, 8 warps (2x4)
__global__ void __launch_bounds__(256) gemm_s1() {
    __shared__ __nv_bfloat16 Qa[2][64][40];
    __shared__ __nv_bfloat16 Ks[2][128][40];
    __shared__ float epi[8][16][16];
    uint32_t sQ = smem_u32(&Qa[0][0][0]);
    uint32_t sK = smem_u32(&Ks[0][0][0]);

    int b = blockIdx.y;
    int col0 = blockIdx.x * 128;
    int tid = threadIdx.x;
    int w = tid >> 5, lane = tid & 31;
    int wm = w >> 2, wn = w & 3;

    wmma::fragment<wmma::accumulator,16,16,16,float> acc[2][2];
    #pragma unroll
    for (int i = 0; i < 2; i++)
        #pragma unroll
        for (int j = 0; j < 2; j++) wmma::fill_fragment(acc[i][j], 0.f);

    #define S1_STAGE(kc, bb) {                                                     \
        {   int ar = tid >> 2, ac = (tid & 3) * 8;                                 \
            CPA16(sQ + (uint32_t)(bb)*5120u + (uint32_t)ar*80u + (uint32_t)ac*2u,  \
                  g_qap + (size_t)ar*DD + (kc) + ac); }                            \
        _Pragma("unroll")                                                          \
        for (int r = 0; r < 2; r++) {                                              \
            int idx = tid + r*256;                                                 \
            int kr = idx >> 2, kcc = (idx & 3) * 8;                                \
            CPA16(sK + (uint32_t)(bb)*10240u + (uint32_t)kr*80u + (uint32_t)kcc*2u,\
                  g_xb + (size_t)(b*NT + col0 + kr)*DD + (kc) + kcc);              \
        }                                                                          \
        CPA_COMMIT(); }

    S1_STAGE(0, 0);
    for (int s = 0; s < 8; s++) {
        CPA_WAIT(0);
        __syncthreads();
        if (s < 7) S1_STAGE((s+1)*32, (s+1)&1);
        int bb = s & 1;
        #pragma unroll
        for (int kk = 0; kk < 2; kk++) {
            wmma::fragment<wmma::matrix_a,16,16,16,__nv_bfloat16,wmma::row_major> af[2];
            wmma::fragment<wmma::matrix_b,16,16,16,__nv_bfloat16,wmma::col_major> bf[2];
            #pragma unroll
            for (int i = 0; i < 2; i++)
                wmma::load_matrix_sync(af[i], &Qa[bb][wm*32 + i*16][kk*16], 40);
            #pragma unroll
            for (int j = 0; j < 2; j++)
                wmma::load_matrix_sync(bf[j], &Ks[bb][wn*32 + j*16][kk*16], 40);
            #pragma unroll
            for (int i = 0; i < 2; i++)
                #pragma unroll
                for (int j = 0; j < 2; j++)
                    wmma::mma_sync(acc[i][j], af[i], bf[j], acc[i][j]);
        }
    }
    #undef S1_STAGE

    float* outb = g_S1 + (size_t)b*NA*NT;
    #pragma unroll
    for (int i = 0; i < 2; i++)
        #pragma unroll
        for (int j = 0; j < 2; j++) {
            wmma::store_matrix_sync(&epi[w][0][0], acc[i][j], 16, wmma::mem_row_major);
            __syncwarp();
            #pragma unroll
            for (int e = 0; e < 2; e++) {
                int idx2 = lane + e*32;
                int r = idx2 >> 2, c4 = (idx2 & 3) * 4;
                int ga = wm*32 + i*16 + r;
                int gt = col0 + wn*32 + j*16 + c4;
                *(float4*)(outb + (size_t)ga*NT + gt) = *(float4*)(&epi[w][r][c4]);
            }
            __syncwarp();
        }
}

// ---------------- stage-1 softmax over N=4096 (smem row cache) --------------
__global__ void softmax1() {
    __shared__ float rowc[NT];
    __shared__ float red[8];
    int row = blockIdx.x;
    const float* s = g_S1 + (size_t)row*NT;
    __nv_bfloat16* p = g_P1 + (size_t)row*NT;
    int t = threadIdx.x;

    float m = -1e30f;
    for (int i = t; i < NT/4; i += 256) {
        float4 v = *(const float4*)(s + i*4);
        *(float4*)(rowc + i*4) = v;
        m = fmaxf(fmaxf(m, fmaxf(v.x, v.y)), fmaxf(v.z, v.w));
    }
    #pragma unroll
    for (int o = 16; o; o >>= 1) m = fmaxf(m, __shfl_xor_sync(0xffffffffu, m, o));
    if ((t & 31) == 0) red[t >> 5] = m;
    __syncthreads();
    float gm = red[0];
    #pragma unroll
    for (int i = 1; i < 8; i++) gm = fmaxf(gm, red[i]);
    __syncthreads();

    float sum = 0.f;
    for (int i = t; i < NT; i += 256) sum += __expf(rowc[i] - gm);
    #pragma unroll
    for (int o = 16; o; o >>= 1) sum += __shfl_xor_sync(0xffffffffu, sum, o);
    if ((t & 31) == 0) red[t >> 5] = sum;
    __syncthreads();
    float gs = 0.f;
    #pragma unroll
    for (int i = 0; i < 8; i++) gs += red[i];
    float inv = 1.f / gs;
    for (int i = t; i < NT/4; i += 256) {
        float4 v = *(const float4*)(rowc + i*4);
        __nv_bfloat16 t4[4] = {
            __float2bfloat16(__expf(v.x - gm) * inv),
            __float2bfloat16(__expf(v.y - gm) * inv),
            __float2bfloat16(__expf(v.z - gm) * inv),
            __float2bfloat16(__expf(v.w - gm) * inv)};
        *(uint2*)(p + i*4) = *(uint2*)t4;
    }
}

// ---------------- u partials: split-K over tokens (u = P1 @ x) ---------------
__global__ void __launch_bounds__(256) gemm_va0() {
    __shared__ __align__(16) char smva[44032];
    __nv_bfloat16 (*Ps)[64][40]  = ( __nv_bfloat16(*)[64][40])  smva;          // 2x5120
    __nv_bfloat16 (*Vs)[32][264] = ( __nv_bfloat16(*)[32][264])(smva + 10240); // 2x16896
    float (*epi)[16][16]         = ( float(*)[16][16])          smva;          // reuse Ps
    uint32_t sP = smem_u32(smva), sV = sP + 10240u;

    int split = blockIdx.x, b = blockIdx.y;
    int tok0 = split * 512;
    int tid = threadIdx.x;
    int w = tid >> 5, lane = tid & 31;
    int wm = w >> 2, wn = w & 3;

    wmma::fragment<wmma::accumulator,16,16,16,float> acc[2][4];
    #pragma unroll
    for (int i = 0; i < 2; i++)
        #pragma unroll
        for (int j = 0; j < 4; j++) wmma::fill_fragment(acc[i][j], 0.f);

    #define VA_STAGE(kc, bb) {                                                     \
        {   int pr = tid >> 2, pc = (tid & 3) * 8;                                 \
            CPA16(sP + (uint32_t)(bb)*5120u + (uint32_t)pr*80u + (uint32_t)pc*2u,  \
                  g_P1 + (size_t)b*NA*NT + (size_t)pr*NT + tok0 + (kc) + pc); }    \
        _Pragma("unroll")                                                          \
        for (int r = 0; r < 4; r++) {                                              \
            int idx = tid + r*256;                                                 \
            int vr = idx >> 5, vc = (idx & 31) * 8;                                \
            CPA16(sV + (uint32_t)(bb)*16896u + (uint32_t)vr*528u + (uint32_t)vc*2u,\
                  g_xb + (size_t)(b*NT + tok0 + (kc) + vr)*DD + vc);               \
        }                                                                          \
        CPA_COMMIT(); }

    VA_STAGE(0, 0);
    for (int s = 0; s < 16; s++) {
        CPA_WAIT(0);
        __syncthreads();
        if (s < 15) VA_STAGE((s+1)*32, (s+1)&1);
        int bb = s & 1;
        #pragma unroll
        for (int kk = 0; kk < 2; kk++) {
            wmma::fragment<wmma::matrix_a,16,16,16,__nv_bfloat16,wmma::row_major> af[2];
            wmma::fragment<wmma::matrix_b,16,16,16,__nv_bfloat16,wmma::row_major> bf[4];
            #pragma unroll
            for (int i = 0; i < 2; i++)
                wmma::load_matrix_sync(af[i], &Ps[bb][wm*32 + i*16][kk*16], 40);
            #pragma unroll
            for (int j = 0; j < 4; j++)
                wmma::load_matrix_sync(bf[j], &Vs[bb][kk*16][wn*64 + j*16], 264);
            #pragma unroll
            for (int i = 0; i < 2; i++)
                #pragma unroll
                for (int j = 0; j < 4; j++)
                    wmma::mma_sync(acc[i][j], af[i], bf[j], acc[i][j]);
        }
    }
    #undef VA_STAGE
    __syncthreads();

    float* outb = g_vap + (size_t)(b*8 + split)*NA*DD;
    #pragma unroll
    for (int i = 0; i < 2; i++)
        #pragma unroll
        for (int j = 0; j < 4; j++) {
            wmma::store_matrix_sync(&epi[w][0][0], acc[i][j], 16, wmma::mem_row_major);
            __syncwarp();
            #pragma unroll
            for (int e = 0; e < 2; e++) {
                int idx2 = lane + e*32;
                int r = idx2 >> 2, c4 = (idx2 & 3) * 4;
                int ga = wm*32 + i*16 + r;
                int gd = wn*64 + j*16 + c4;
                *(float4*)(outb + (size_t)ga*DD + gd) = *(float4*)(&epi[w][r][c4]);
            }
            __syncwarp();
        }
}

// ---------------- fc1: sum partials, then va = u @ Wvf + bvf ----------------
__global__ void fc1k() {
    __shared__ float r0[DD];
    int row = blockIdx.x;  // b*NA + a
    int b = row >> 6, a = row & 63;
    int i = threadIdx.x;
    float acc = 0.f;
    #pragma unroll
    for (int sp = 0; sp < 8; sp++)
        acc += g_vap[(size_t)(b*8 + sp)*NA*DD + (size_t)a*DD + i];
    r0[i] = acc;
    __syncthreads();
    int o = threadIdx.x;
    float s = g_bvf[o];
    #pragma unroll 8
    for (int d = 0; d < DD; d++) s += r0[d] * g_Wvf[d*DD + o];
    g_va[(size_t)row*DD + o] = __float2bfloat16(s);
}

// ---------------- stage 2: logits(x@Ka') + dbias -> softmax -> @ va ---------
__global__ void __launch_bounds__(256) stage2() {
    extern __shared__ __align__(16) char sm2[];
    __nv_bfloat16 (*Qs)[128][40] = ( __nv_bfloat16(*)[128][40]) sm2;             // 20480
    __nv_bfloat16 (*Ka)[64][40]  = ( __nv_bfloat16(*)[64][40]) (sm2 + 20480);    // 10240
    float* logits                = ( float*)                   (sm2 + 30720);    // 34816
    __nv_bfloat16 (*Vs)[264]     = ( __nv_bfloat16(*)[264])    (sm2 + 65536);    // 33792
    __nv_bfloat16 (*Pm)[72]      = ( __nv_bfloat16(*)[72])     sm2;              // reuse Qs
    float (*epi)[16][16]         = ( float(*)[16][16])         (sm2 + 20480);    // reuse Ka
    __shared__ float dbs[NA];
    uint32_t sQ = smem_u32(sm2), sKa = sQ + 20480u, sV = sQ + 65536u;

    int b = blockIdx.y, t0 = blockIdx.x * 128;
    int tid = threadIdx.x;
    int w = tid >> 5, lane = tid & 31;

    if (tid < NA) dbs[tid] = g_dbias[tid];

    // async prefetch va tile [64,256] into Vs
    #pragma unroll
    for (int r = 0; r < 8; r++) {
        int idx = tid + r*256;
        int vr = idx >> 5, vc = (idx & 31) * 8;
        CPA16(sV + (uint32_t)vr*528u + (uint32_t)vc*2u,
              g_va + (size_t)(b*NA + vr)*DD + vc);
    }
    CPA_COMMIT();

    // --- phase A: logits[128,64] = x_tile @ Ka'^T, warps 4x2, warp 32x32 ---
    {
        int wm = w >> 1, wn = w & 1;
        wmma::fragment<wmma::accumulator,16,16,16,float> acc[2][2];
        #pragma unroll
        for (int i = 0; i < 2; i++)
            #pragma unroll
            for (int j = 0; j < 2; j++) wmma::fill_fragment(acc[i][j], 0.f);

        #define S2_STAGE(kc, bb) {                                                 \
            _Pragma("unroll")                                                      \
            for (int r = 0; r < 2; r++) {                                          \
                int idx = tid + r*256;                                             \
                int qr = idx >> 2, qc = (idx & 3) * 8;                             \
                CPA16(sQ + (uint32_t)(bb)*10240u + (uint32_t)qr*80u + (uint32_t)qc*2u, \
                      g_xb + (size_t)(b*NT + t0 + qr)*DD + (kc) + qc);             \
            }                                                                      \
            {   int ar = tid >> 2, ac = (tid & 3) * 8;                             \
                CPA16(sKa + (uint32_t)(bb)*5120u + (uint32_t)ar*80u + (uint32_t)ac*2u, \
                      g_kat + (size_t)ar*DD + (kc) + ac); }                        \
            CPA_COMMIT(); }

        S2_STAGE(0, 0);
        for (int s = 0; s < 8; s++) {
            CPA_WAIT(0);
            __syncthreads();
            if (s < 7) S2_STAGE((s+1)*32, (s+1)&1);
            int bb = s & 1;
            #pragma unroll
            for (int kk = 0; kk < 2; kk++) {
                wmma::fragment<wmma::matrix_a,16,16,16,__nv_bfloat16,wmma::row_major> af[2];
                wmma::fragment<wmma::matrix_b,16,16,16,__nv_bfloat16,wmma::col_major> bf[2];
                #pragma unroll
                for (int i = 0; i < 2; i++)
                    wmma::load_matrix_sync(af[i], &Qs[bb][wm*32 + i*16][kk*16], 40);
                #pragma unroll
                for (int j = 0; j < 2; j++)
                    wmma::load_matrix_sync(bf[j], &Ka[bb][wn*32 + j*16][kk*16], 40);
                #pragma unroll
                for (int i = 0; i < 2; i++)
                    #pragma unroll
                    for (int j = 0; j < 2; j++)
                        wmma::mma_sync(acc[i][j], af[i], bf[j], acc[i][j]);
            }
        }
        #undef S2_STAGE
        __syncthreads();
        #pragma unroll
        for (int i = 0; i < 2; i++)
            #pragma unroll
            for (int j = 0; j < 2; j++)
                wmma::store_matrix_sync(logits + (wm*32 + i*16)*68 + wn*32 + j*16,
                                        acc[i][j], 68, wmma::mem_row_major);
    }
    __syncthreads();

    // --- phase B: per-row softmax over 64 agents (+dbias) -> Pm ---
    if (tid < 128) {
        const float* lr = logits + tid*68;
        float lv[64];
        #pragma unroll 8
        for (int c = 0; c < 64; c++) lv[c] = lr[c] + dbs[c];
        float m = -1e30f;
        #pragma unroll 8
        for (int c = 0; c < 64; c++) m = fmaxf(m, lv[c]);
        float sum = 0.f;
        #pragma unroll 8
        for (int c = 0; c < 64; c++) sum += __expf(lv[c] - m);
        float inv = 1.f / sum;
        #pragma unroll 8
        for (int c = 0; c < 64; c++)
            Pm[tid][c] = __float2bfloat16(__expf(lv[c] - m) * inv);
    }
    __syncthreads();

    // --- phase C: mid[128,256] = Pm[128,64] @ Vs[64,256]; two N passes ---
    {
        int wm = w >> 1, wn = w & 1;
        for (int nc = 0; nc < 2; nc++) {
            wmma::fragment<wmma::accumulator,16,16,16,float> acc[2][4];
            #pragma unroll
            for (int i = 0; i < 2; i++)
                #pragma unroll
                for (int j = 0; j < 4; j++) wmma::fill_fragment(acc[i][j], 0.f);
            #pragma unroll
            for (int kk = 0; kk < 4; kk++) {
                wmma::fragment<wmma::matrix_a,16,16,16,__nv_bfloat16,wmma::row_major> af[2];
                wmma::fragment<wmma::matrix_b,16,16,16,__nv_bfloat16,wmma::row_major> bf[4];
                #pragma unroll
                for (int i = 0; i < 2; i++)
                    wmma::load_matrix_sync(af[i], &Pm[wm*32 + i*16][kk*16], 72);
                #pragma unroll
                for (int j = 0; j < 4; j++)
                    wmma::load_matrix_sync(bf[j], &Vs[kk*16][nc*128 + wn*64 + j*16], 264);
                #pragma unroll
                for (int i = 0; i < 2; i++)
                    #pragma unroll
                    for (int j = 0; j < 4; j++)
                        wmma::mma_sync(acc[i][j], af[i], bf[j], acc[i][j]);
            }
            int r = lane >> 1, c8 = (lane & 1) * 8;
            #pragma unroll
            for (int i = 0; i < 2; i++)
                #pragma unroll
                for (int j = 0; j < 4; j++) {
                    wmma::store_matrix_sync(&epi[w][0][0], acc[i][j], 16, wmma::mem_row_major);
                    __syncwarp();
                    int grow = t0 + wm*32 + i*16 + r;
                    int gcol = nc*128 + wn*64 + j*16 + c8;
                    __nv_bfloat16 tmp[8];
                    #pragma unroll
                    for (int e = 0; e < 8; e++)
                        tmp[e] = __float2bfloat16(epi[w][r][c8+e]);
                    *(uint4*)(g_mid + (size_t)(b*NT + grow)*DD + gcol) = *(uint4*)tmp;
                    __syncwarp();
                }
        }
    }
}

// ---------------- fc2 + bias + residual -> out ------------------------------
__global__ void __launch_bounds__(128) gemm_fc2(const float* __restrict__ bias,
                                                const float* __restrict__ x,
                                                float* __restrict__ out) {
    extern __shared__ __align__(16) char smf[];
    __nv_bfloat16 (*As)[128][72] = (__nv_bfloat16(*)[128][72]) smf;
    __nv_bfloat16 (*Bs)[64][136] = (__nv_bfloat16(*)[64][136])(smf + 36864);
    float (*epi)[16][16]         = (float(*)[16][16])          smf;
    uint32_t sA = smem_u32(smf), sB = sA + 36864u;

    int tid = threadIdx.x;
    int w = tid >> 5, lane = tid & 31;
    int wm = w >> 1, wn = w & 1;
    int row0 = blockIdx.y * 128, col0 = blockIdx.x * 128;

    wmma::fragment<wmma::accumulator,16,16,16,float> acc[4][4];
    #pragma unroll
    for (int i = 0; i < 4; i++)
        #pragma unroll
        for (int j = 0; j < 4; j++) wmma::fill_fragment(acc[i][j], 0.f);

    #define FC2_STAGE(kc, bb) {                                                    \
        _Pragma("unroll")                                                          \
        for (int r = 0; r < 8; r++) {                                              \
            int idx = tid + r*128;                                                 \
            int ar = idx >> 3, ac = (idx & 7) * 8;                                 \
            CPA16(sA + (uint32_t)(bb)*18432u + (uint32_t)ar*144u + (uint32_t)ac*2u,\
                  g_mid + (size_t)(row0+ar)*DD + (kc) + ac);                       \
        }                                                                          \
        _Pragma("unroll")                                                          \
        for (int r = 0; r < 8; r++) {                                              \
            int idx = tid + r*128;                                                 \
            int br = idx >> 4, bc = (idx & 15) * 8;                                \
            CPA16(sB + (uint32_t)(bb)*17408u + (uint32_t)br*272u + (uint32_t)bc*2u,\
                  g_Wfc2 + (size_t)((kc)+br)*DD + col0 + bc);                      \
        }                                                                          \
        CPA_COMMIT(); }

    FC2_STAGE(0, 0);
    for (int s = 0; s < 4; s++) {
        CPA_WAIT(0);
        __syncthreads();
        if (s < 3) FC2_STAGE((s+1)*64, (s+1)&1);
        int bb = s & 1;
        #pragma unroll
        for (int k4 = 0; k4 < 4; k4++) {
            wmma::fragment<wmma::matrix_a,16,16,16,__nv_bfloat16,wmma::row_major> af[4];
            wmma::fragment<wmma::matrix_b,16,16,16,__nv_bfloat16,wmma::row_major> bf[4];
            #pragma unroll
            for (int i = 0; i < 4; i++)
                wmma::load_matrix_sync(af[i], &As[bb][wm*64 + i*16][k4*16], 72);
            #pragma unroll
            for (int j = 0; j < 4; j++)
                wmma::load_matrix_sync(bf[j], &Bs[bb][k4*16][wn*64 + j*16], 136);
            #pragma unroll
            for (int i = 0; i < 4; i++)
                #pragma unroll
                for (int j = 0; j < 4; j++)
                    wmma::mma_sync(acc[i][j], af[i], bf[j], acc[i][j]);
        }
    }
    #undef FC2_STAGE
    __syncthreads();

    int r = lane >> 1, c8 = (lane & 1) * 8;
    #pragma unroll
    for (int i = 0; i < 4; i++)
        #pragma unroll
        for (int j = 0; j < 4; j++) {
            wmma::store_matrix_sync(&epi[w][0][0], acc[i][j], 16, wmma::mem_row_major);
            __syncwarp();
            int gr = row0 + wm*64 + i*16 + r;
            int gc = col0 + wn*64 + j*16 + c8;
            size_t gi = (size_t)gr*DD + gc;
            float o0[4], o1[4];
            #pragma unroll
            for (int e = 0; e < 4; e++) o0[e] = epi[w][r][c8+e]   + bias[gc+e]   + x[gi+e];
            #pragma unroll
            for (int e = 0; e < 4; e++) o1[e] = epi[w][r][c8+4+e] + bias[gc+4+e] + x[gi+4+e];
            *(float4*)(out + gi)     = *(float4*)o0;
            *(float4*)(out + gi + 4) = *(float4*)o1;
            __syncwarp();
        }
}

// ---------------- launcher ---------------------------------------------------
#define BIG_SMEM 71680

extern "C" void kernel_launch(void* const* d_in, const int* in_sizes, int n_in,
                              void* d_out, int out_size) {
    const float* agent = (const float*)d_in[0];
    const float* x     = (const float*)d_in[1];
    const float* Wqkv  = (const float*)d_in[2];
    const float* bqkv  = (const float*)d_in[3];
    const float* Wag   = (const float*)d_in[4];
    const float* bag   = (const float*)d_in[5];
    const float* Wfc1  = (const float*)d_in[6];
    const float* bfc1  = (const float*)d_in[7];
    const float* Wfc2  = (const float*)d_in[8];
    const float* bfc2  = (const float*)d_in[9];
    float* out = (float*)d_out;

    cudaFuncSetAttribute(stage2,   cudaFuncAttributeMaxDynamicSharedMemorySize, 99328);
    cudaFuncSetAttribute(gemm_fc2, cudaFuncAttributeMaxDynamicSharedMemorySize, BIG_SMEM);

    conv_inputs<<<2048, 256>>>(x, Wfc2, Wqkv, Wfc1);
    agent_proj<<<64, 512>>>(agent, Wag, bag);
    proj_agents<<<dim3(4, 2), 128>>>();
    wvf_wmma<<<dim3(2, 2), 256>>>();
    dbias_k<<<64, 256>>>(bqkv);
    bvf_k<<<1, 256>>>(Wfc1, bqkv, bfc1);
    gemm_s1<<<dim3(32, 8), 256>>>();
    softmax1<<<512, 256>>>();
    gemm_va0<<<dim3(8, 8), 256>>>();
    fc1k<<<512, 256>>>();
    stage2<<<dim3(32, 8), 256, 99328>>>();
    gemm_fc2<<<dim3(2, 256), 128, BIG_SMEM>>>(bfc2, x, out);
}

// round 8
// speedup vs baseline: 1.3735x; 1.1244x over previous
#include <cuda_runtime.h>
#include <cuda_bf16.h>
#include <mma.h>
#include <cstdint>

using namespace nvcuda;

#define NB 8
#define NT 4096
#define NA 64
#define DD 256
#define MTOK (NB*NT)
#define W3 (3*DD)

// ---------------- scratch (device globals; no allocations allowed) ----------
__device__ __nv_bfloat16 g_xb[MTOK*DD];              // x in bf16
__device__ __nv_bfloat16 g_Wfc2[DD*DD];              // W_fc2 bf16 [K,N]
__device__ __nv_bfloat16 g_Wqkvb[DD*W3];             // W_qkv bf16 [K, 3N]
__device__ __nv_bfloat16 g_Wfc1b[DD*DD];             // W_fc1 bf16 [K,N]
__device__ __nv_bfloat16 g_qasb[NA*DD];              // qa_s bf16 (scale folded)
__device__ __nv_bfloat16 g_kasb[NA*DD];              // ka_s bf16 (scale folded)
__device__ float        g_kaf[NA*DD];                // ka_s fp32 (for dbias)
__device__ __nv_bfloat16 g_qap[NA*DD];               // qa' = qa_s @ Wk^T, bf16
__device__ __nv_bfloat16 g_kat[NA*DD];               // Ka' [a,i] bf16
__device__ float        g_dbias[NA];                 // bq . ka_s
__device__ float        g_Wvf[DD*DD];                // Wv @ Wfc1, fp32
__device__ float        g_bvf[DD];                   // bv@Wfc1 + bfc1
__device__ float        g_S1[NB*NA*NT];              // stage-1 logits
__device__ __nv_bfloat16 g_P1[NB*NA*NT];             // stage-1 probs
__device__ float        g_vap[NB*8*NA*DD];           // split-K partials of P1@x
__device__ __nv_bfloat16 g_va[NB*NA*DD];             // u@Wvf+bvf, bf16
__device__ __nv_bfloat16 g_mid[MTOK*DD];             // attn2 @ va, bf16

// ---------------- cp.async helpers ------------------------------------------
__device__ __forceinline__ uint32_t smem_u32(const void* p) {
    uint32_t a;
    asm("{ .reg .u64 t; cvta.to.shared.u64 t, %1; cvt.u32.u64 %0, t; }" : "=r"(a) : "l"(p));
    return a;
}
#define CPA16(s, g)  asm volatile("cp.async.cg.shared.global [%0], [%1], 16;" :: "r"(s), "l"(g))
#define CPA_COMMIT() asm volatile("cp.async.commit_group;" ::: "memory")
#define CPA_WAIT(n)  asm volatile("cp.async.wait_group %0;" :: "n"(n) : "memory")

// ---------------- input conversion (x, W_fc2, W_qkv, W_fc1) -----------------
__global__ void conv_inputs(const float* __restrict__ x,
                            const float* __restrict__ Wfc2,
                            const float* __restrict__ Wqkv,
                            const float* __restrict__ Wfc1) {
    int stride = gridDim.x * blockDim.x;
    int tid = blockIdx.x * blockDim.x + threadIdx.x;
    for (int i = tid; i < (MTOK*DD)/4; i += stride) {
        float4 v = *(const float4*)(x + i*4);
        __nv_bfloat16 t[4] = {__float2bfloat16(v.x), __float2bfloat16(v.y),
                              __float2bfloat16(v.z), __float2bfloat16(v.w)};
        *(uint2*)(g_xb + i*4) = *(uint2*)t;
    }
    for (int i = tid; i < DD*DD; i += stride)
        g_Wfc2[i] = __float2bfloat16(Wfc2[i]);
    for (int i = tid; i < DD*W3; i += stride)
        g_Wqkvb[i] = __float2bfloat16(Wqkv[i]);
    for (int i = tid; i < DD*DD; i += stride)
        g_Wfc1b[i] = __float2bfloat16(Wfc1[i]);
}

// ---------------- agent projection (scale folded) ---------------------------
__global__ void agent_proj(const float* __restrict__ agent,
                           const float* __restrict__ W,
                           const float* __restrict__ b) {
    __shared__ float arow[DD];
    int a = blockIdx.x;
    for (int i = threadIdx.x; i < DD; i += blockDim.x)
        arow[i] = agent[a*DD + i];
    __syncthreads();
    int o = threadIdx.x;  // 0..511
    float s = 0.f;
    #pragma unroll 8
    for (int d = 0; d < DD; d++)
        s += arow[d] * W[d*2*DD + o];
    s += b[o];
    s *= 0.0625f;  // 256^-0.5
    if (o < DD) {
        g_qasb[a*DD + o] = __float2bfloat16(s);
    } else {
        g_kasb[a*DD + (o-DD)] = __float2bfloat16(s);
        g_kaf [a*DD + (o-DD)] = s;
    }
}

// ---------------- proj_agents (cp.async-staged WMMA) -------------------------
// C[64, icol 64-tile] = A[64,256] @ Wblock^T;  grid (4 i-tiles, 2 sel)
// sel 0: qa' = qa_s @ Wk^T ; sel 1: Ka' = ka_s @ Wq^T
// 256 threads, 8 warps (2x4), warp 32x16, BK=32, 2-stage, one sync/iter
__global__ void __launch_bounds__(256) proj_agents() {
    __shared__ __nv_bfloat16 Aa[2][64][40];
    __shared__ __nv_bfloat16 Ws[2][64][40];
    __shared__ float epi[8][16][16];
    uint32_t sA = smem_u32(&Aa[0][0][0]);
    uint32_t sW = smem_u32(&Ws[0][0][0]);

    int sel = blockIdx.y;
    int col0 = blockIdx.x * 64;                 // i-tile within DD
    const __nv_bfloat16* A  = sel ? g_kasb : g_qasb;
    const __nv_bfloat16* Bb = g_Wqkvb + (sel ? 0 : DD);
    __nv_bfloat16* C = sel ? g_kat : g_qap;
    int tid = threadIdx.x;
    int w = tid >> 5, lane = tid & 31;
    int wm = w >> 2, wn = w & 3;                // 2x4, warp 32x16

    wmma::fragment<wmma::accumulator,16,16,16,float> acc[2];
    #pragma unroll
    for (int i = 0; i < 2; i++) wmma::fill_fragment(acc[i], 0.f);

    #define PA_STAGE(kc, bb) {                                                     \
        {   int ar = tid >> 2, ac = (tid & 3) * 8;                                 \
            CPA16(sA + (uint32_t)(bb)*5120u + (uint32_t)ar*80u + (uint32_t)ac*2u,  \
                  A + (size_t)ar*DD + (kc) + ac); }                                \
        {   int wr = tid >> 2, wc = (tid & 3) * 8;                                 \
            CPA16(sW + (uint32_t)(bb)*5120u + (uint32_t)wr*80u + (uint32_t)wc*2u,  \
                  Bb + (size_t)(col0 + wr)*W3 + (kc) + wc); }                      \
        CPA_COMMIT(); }

    PA_STAGE(0, 0);
    for (int s = 0; s < 8; s++) {
        CPA_WAIT(0);
        __syncthreads();
        if (s < 7) PA_STAGE((s+1)*32, (s+1)&1);
        int bb = s & 1;
        #pragma unroll
        for (int kk = 0; kk < 2; kk++) {
            wmma::fragment<wmma::matrix_a,16,16,16,__nv_bfloat16,wmma::row_major> af[2];
            wmma::fragment<wmma::matrix_b,16,16,16,__nv_bfloat16,wmma::col_major> bf;
            #pragma unroll
            for (int i = 0; i < 2; i++)
                wmma::load_matrix_sync(af[i], &Aa[bb][wm*32 + i*16][kk*16], 40);
            wmma::load_matrix_sync(bf, &Ws[bb][wn*16][kk*16], 40);
            #pragma unroll
            for (int i = 0; i < 2; i++)
                wmma::mma_sync(acc[i], af[i], bf, acc[i]);
        }
    }
    #undef PA_STAGE

    #pragma unroll
    for (int i = 0; i < 2; i++) {
        wmma::store_matrix_sync(&epi[w][0][0], acc[i], 16, wmma::mem_row_major);
        __syncwarp();
        if (lane < 16) {
            int a = wm*32 + i*16 + lane;
            __nv_bfloat16 t8[8];
            #pragma unroll
            for (int g = 0; g < 2; g++) {
                #pragma unroll
                for (int e = 0; e < 8; e++)
                    t8[e] = __float2bfloat16(epi[w][lane][g*8+e]);
                *(uint4*)(C + (size_t)a*DD + col0 + wn*16 + g*8) = *(uint4*)t8;
            }
        }
        __syncwarp();
    }
}

// ---------------- Wvf = Wv @ Wfc1 (cp.async-staged, fp32 out) ----------------
// clone of gemm_fc2 skeleton: tile 128x128, BK=64, 2-stage, warp 64x64
__global__ void __launch_bounds__(128) wvf_gemm() {
    extern __shared__ __align__(16) char smv[];
    __nv_bfloat16 (*As)[128][72] = (__nv_bfloat16(*)[128][72]) smv;
    __nv_bfloat16 (*Bs)[64][136] = (__nv_bfloat16(*)[64][136])(smv + 36864);
    float (*epi)[16][16]         = (float(*)[16][16])          smv;
    uint32_t sA = smem_u32(smv), sB = sA + 36864u;

    int tid = threadIdx.x;
    int w = tid >> 5, lane = tid & 31;
    int wm = w >> 1, wn = w & 1;
    int row0 = blockIdx.y * 128, col0 = blockIdx.x * 128;

    wmma::fragment<wmma::accumulator,16,16,16,float> acc[4][4];
    #pragma unroll
    for (int i = 0; i < 4; i++)
        #pragma unroll
        for (int j = 0; j < 4; j++) wmma::fill_fragment(acc[i][j], 0.f);

    #define WVF_STAGE(kc, bb) {                                                    \
        _Pragma("unroll")                                                          \
        for (int r = 0; r < 8; r++) {                                              \
            int idx = tid + r*128;                                                 \
            int ar = idx >> 3, ac = (idx & 7) * 8;                                 \
            CPA16(sA + (uint32_t)(bb)*18432u + (uint32_t)ar*144u + (uint32_t)ac*2u,\
                  g_Wqkvb + (size_t)(row0+ar)*W3 + 2*DD + (kc) + ac);              \
        }                                                                          \
        _Pragma("unroll")                                                          \
        for (int r = 0; r < 8; r++) {                                              \
            int idx = tid + r*128;                                                 \
            int br = idx >> 4, bc = (idx & 15) * 8;                                \
            CPA16(sB + (uint32_t)(bb)*17408u + (uint32_t)br*272u + (uint32_t)bc*2u,\
                  g_Wfc1b + (size_t)((kc)+br)*DD + col0 + bc);                     \
        }                                                                          \
        CPA_COMMIT(); }

    WVF_STAGE(0, 0);
    for (int s = 0; s < 4; s++) {
        CPA_WAIT(0);
        __syncthreads();
        if (s < 3) WVF_STAGE((s+1)*64, (s+1)&1);
        int bb = s & 1;
        #pragma unroll
        for (int k4 = 0; k4 < 4; k4++) {
            wmma::fragment<wmma::matrix_a,16,16,16,__nv_bfloat16,wmma::row_major> af[4];
            wmma::fragment<wmma::matrix_b,16,16,16,__nv_bfloat16,wmma::row_major> bf[4];
            #pragma unroll
            for (int i = 0; i < 4; i++)
                wmma::load_matrix_sync(af[i], &As[bb][wm*64 + i*16][k4*16], 72);
            #pragma unroll
            for (int j = 0; j < 4; j++)
                wmma::load_matrix_sync(bf[j], &Bs[bb][k4*16][wn*64 + j*16], 136);
            #pragma unroll
            for (int i = 0; i < 4; i++)
                #pragma unroll
                for (int j = 0; j < 4; j++)
                    wmma::mma_sync(acc[i][j], af[i], bf[j], acc[i][j]);
        }
    }
    #undef WVF_STAGE
    __syncthreads();

    int r = lane >> 1, c8 = (lane & 1) * 8;
    #pragma unroll
    for (int i = 0; i < 4; i++)
        #pragma unroll
        for (int j = 0; j < 4; j++) {
            wmma::store_matrix_sync(&epi[w][0][0], acc[i][j], 16, wmma::mem_row_major);
            __syncwarp();
            int gr = row0 + wm*64 + i*16 + r;
            int gc = col0 + wn*64 + j*16 + c8;
            *(float4*)(g_Wvf + (size_t)gr*DD + gc)     = *(float4*)(&epi[w][r][c8]);
            *(float4*)(g_Wvf + (size_t)gr*DD + gc + 4) = *(float4*)(&epi[w][r][c8+4]);
            __syncwarp();
        }
}

// ---------------- dbias[a] = bq . ka_s ; bvf = bv@Wfc1 + bfc1 ---------------
__global__ void dbias_k(const float* __restrict__ bqkv) {
    __shared__ float red[256];
    int a = blockIdx.x, i = threadIdx.x;
    red[i] = bqkv[i] * g_kaf[a*DD + i];
    __syncthreads();
    for (int st = 128; st > 0; st >>= 1) {
        if (i < st) red[i] += red[i + st];
        __syncthreads();
    }
    if (i == 0) g_dbias[a] = red[0];
}
__global__ void bvf_k(const float* __restrict__ Wfc1,
                      const float* __restrict__ bqkv, const float* __restrict__ bfc1) {
    int j = threadIdx.x;
    float t = bfc1[j];
    #pragma unroll 8
    for (int o = 0; o < DD; o++)
        t += bqkv[2*DD + o] * Wfc1[o*DD + j];
    g_bvf[j] = t;
}

// ---------------- stage-1 logits: S1[b] = qa' @ x_b^T -----------------------
// tile 64x128, BK=32, 2-stage cp.async, one sync/iter, 8 warps (2x4)
__global__ void __launch_bounds__(256) gemm_s1() {
    __shared__ __nv_bfloat16 Qa[2][64][40];
    __shared__ __nv_bfloat16 Ks[2][128][40];
    __shared__ float epi[8][16][16];
    uint32_t sQ = smem_u32(&Qa[0][0][0]);
    uint32_t sK = smem_u32(&Ks[0][0][0]);

    int b = blockIdx.y;
    int col0 = blockIdx.x * 128;
    int tid = threadIdx.x;
    int w = tid >> 5, lane = tid & 31;
    int wm = w >> 2, wn = w & 3;

    wmma::fragment<wmma::accumulator,16,16,16,float> acc[2][2];
    #pragma unroll
    for (int i = 0; i < 2; i++)
        #pragma unroll
        for (int j = 0; j < 2; j++) wmma::fill_fragment(acc[i][j], 0.f);

    #define S1_STAGE(kc, bb) {                                                     \
        {   int ar = tid >> 2, ac = (tid & 3) * 8;                                 \
            CPA16(sQ + (uint32_t)(bb)*5120u + (uint32_t)ar*80u + (uint32_t)ac*2u,  \
                  g_qap + (size_t)ar*DD + (kc) + ac); }                            \
        _Pragma("unroll")                                                          \
        for (int r = 0; r < 2; r++) {                                              \
            int idx = tid + r*256;                                                 \
            int kr = idx >> 2, kcc = (idx & 3) * 8;                                \
            CPA16(sK + (uint32_t)(bb)*10240u + (uint32_t)kr*80u + (uint32_t)kcc*2u,\
                  g_xb + (size_t)(b*NT + col0 + kr)*DD + (kc) + kcc);              \
        }                                                                          \
        CPA_COMMIT(); }

    S1_STAGE(0, 0);
    for (int s = 0; s < 8; s++) {
        CPA_WAIT(0);
        __syncthreads();
        if (s < 7) S1_STAGE((s+1)*32, (s+1)&1);
        int bb = s & 1;
        #pragma unroll
        for (int kk = 0; kk < 2; kk++) {
            wmma::fragment<wmma::matrix_a,16,16,16,__nv_bfloat16,wmma::row_major> af[2];
            wmma::fragment<wmma::matrix_b,16,16,16,__nv_bfloat16,wmma::col_major> bf[2];
            #pragma unroll
            for (int i = 0; i < 2; i++)
                wmma::load_matrix_sync(af[i], &Qa[bb][wm*32 + i*16][kk*16], 40);
            #pragma unroll
            for (int j = 0; j < 2; j++)
                wmma::load_matrix_sync(bf[j], &Ks[bb][wn*32 + j*16][kk*16], 40);
            #pragma unroll
            for (int i = 0; i < 2; i++)
                #pragma unroll
                for (int j = 0; j < 2; j++)
                    wmma::mma_sync(acc[i][j], af[i], bf[j], acc[i][j]);
        }
    }
    #undef S1_STAGE

    float* outb = g_S1 + (size_t)b*NA*NT;
    #pragma unroll
    for (int i = 0; i < 2; i++)
        #pragma unroll
        for (int j = 0; j < 2; j++) {
            wmma::store_matrix_sync(&epi[w][0][0], acc[i][j], 16, wmma::mem_row_major);
            __syncwarp();
            #pragma unroll
            for (int e = 0; e < 2; e++) {
                int idx2 = lane + e*32;
                int r = idx2 >> 2, c4 = (idx2 & 3) * 4;
                int ga = wm*32 + i*16 + r;
                int gt = col0 + wn*32 + j*16 + c4;
                *(float4*)(outb + (size_t)ga*NT + gt) = *(float4*)(&epi[w][r][c4]);
            }
            __syncwarp();
        }
}

// ---------------- stage-1 softmax over N=4096 (smem row cache) --------------
__global__ void softmax1() {
    __shared__ float rowc[NT];
    __shared__ float red[8];
    int row = blockIdx.x;
    const float* s = g_S1 + (size_t)row*NT;
    __nv_bfloat16* p = g_P1 + (size_t)row*NT;
    int t = threadIdx.x;

    float m = -1e30f;
    for (int i = t; i < NT/4; i += 256) {
        float4 v = *(const float4*)(s + i*4);
        *(float4*)(rowc + i*4) = v;
        m = fmaxf(fmaxf(m, fmaxf(v.x, v.y)), fmaxf(v.z, v.w));
    }
    #pragma unroll
    for (int o = 16; o; o >>= 1) m = fmaxf(m, __shfl_xor_sync(0xffffffffu, m, o));
    if ((t & 31) == 0) red[t >> 5] = m;
    __syncthreads();
    float gm = red[0];
    #pragma unroll
    for (int i = 1; i < 8; i++) gm = fmaxf(gm, red[i]);
    __syncthreads();

    float sum = 0.f;
    for (int i = t; i < NT; i += 256) sum += __expf(rowc[i] - gm);
    #pragma unroll
    for (int o = 16; o; o >>= 1) sum += __shfl_xor_sync(0xffffffffu, sum, o);
    if ((t & 31) == 0) red[t >> 5] = sum;
    __syncthreads();
    float gs = 0.f;
    #pragma unroll
    for (int i = 0; i < 8; i++) gs += red[i];
    float inv = 1.f / gs;
    for (int i = t; i < NT/4; i += 256) {
        float4 v = *(const float4*)(rowc + i*4);
        __nv_bfloat16 t4[4] = {
            __float2bfloat16(__expf(v.x - gm) * inv),
            __float2bfloat16(__expf(v.y - gm) * inv),
            __float2bfloat16(__expf(v.z - gm) * inv),
            __float2bfloat16(__expf(v.w - gm) * inv)};
        *(uint2*)(p + i*4) = *(uint2*)t4;
    }
}

// ---------------- u partials: split-K over tokens (u = P1 @ x) ---------------
__global__ void __launch_bounds__(256) gemm_va0() {
    __shared__ __align__(16) char smva[44032];
    __nv_bfloat16 (*Ps)[64][40]  = ( __nv_bfloat16(*)[64][40])  smva;          // 2x5120
    __nv_bfloat16 (*Vs)[32][264] = ( __nv_bfloat16(*)[32][264])(smva + 10240); // 2x16896
    float (*epi)[16][16]         = ( float(*)[16][16])          smva;          // reuse Ps
    uint32_t sP = smem_u32(smva), sV = sP + 10240u;

    int split = blockIdx.x, b = blockIdx.y;
    int tok0 = split * 512;
    int tid = threadIdx.x;
    int w = tid >> 5, lane = tid & 31;
    int wm = w >> 2, wn = w & 3;

    wmma::fragment<wmma::accumulator,16,16,16,float> acc[2][4];
    #pragma unroll
    for (int i = 0; i < 2; i++)
        #pragma unroll
        for (int j = 0; j < 4; j++) wmma::fill_fragment(acc[i][j], 0.f);

    #define VA_STAGE(kc, bb) {                                                     \
        {   int pr = tid >> 2, pc = (tid & 3) * 8;                                 \
            CPA16(sP + (uint32_t)(bb)*5120u + (uint32_t)pr*80u + (uint32_t)pc*2u,  \
                  g_P1 + (size_t)b*NA*NT + (size_t)pr*NT + tok0 + (kc) + pc); }    \
        _Pragma("unroll")                                                          \
        for (int r = 0; r < 4; r++) {                                              \
            int idx = tid + r*256;                                                 \
            int vr = idx >> 5, vc = (idx & 31) * 8;                                \
            CPA16(sV + (uint32_t)(bb)*16896u + (uint32_t)vr*528u + (uint32_t)vc*2u,\
                  g_xb + (size_t)(b*NT + tok0 + (kc) + vr)*DD + vc);               \
        }                                                                          \
        CPA_COMMIT(); }

    VA_STAGE(0, 0);
    for (int s = 0; s < 16; s++) {
        CPA_WAIT(0);
        __syncthreads();
        if (s < 15) VA_STAGE((s+1)*32, (s+1)&1);
        int bb = s & 1;
        #pragma unroll
        for (int kk = 0; kk < 2; kk++) {
            wmma::fragment<wmma::matrix_a,16,16,16,__nv_bfloat16,wmma::row_major> af[2];
            wmma::fragment<wmma::matrix_b,16,16,16,__nv_bfloat16,wmma::row_major> bf[4];
            #pragma unroll
            for (int i = 0; i < 2; i++)
                wmma::load_matrix_sync(af[i], &Ps[bb][wm*32 + i*16][kk*16], 40);
            #pragma unroll
            for (int j = 0; j < 4; j++)
                wmma::load_matrix_sync(bf[j], &Vs[bb][kk*16][wn*64 + j*16], 264);
            #pragma unroll
            for (int i = 0; i < 2; i++)
                #pragma unroll
                for (int j = 0; j < 4; j++)
                    wmma::mma_sync(acc[i][j], af[i], bf[j], acc[i][j]);
        }
    }
    #undef VA_STAGE
    __syncthreads();

    float* outb = g_vap + (size_t)(b*8 + split)*NA*DD;
    #pragma unroll
    for (int i = 0; i < 2; i++)
        #pragma unroll
        for (int j = 0; j < 4; j++) {
            wmma::store_matrix_sync(&epi[w][0][0], acc[i][j], 16, wmma::mem_row_major);
            __syncwarp();
            #pragma unroll
            for (int e = 0; e < 2; e++) {
                int idx2 = lane + e*32;
                int r = idx2 >> 2, c4 = (idx2 & 3) * 4;
                int ga = wm*32 + i*16 + r;
                int gd = wn*64 + j*16 + c4;
                *(float4*)(outb + (size_t)ga*DD + gd) = *(float4*)(&epi[w][r][c4]);
            }
            __syncwarp();
        }
}

// ---------------- fc1: sum partials, then va = u @ Wvf + bvf ----------------
__global__ void fc1k() {
    __shared__ float r0[DD];
    int row = blockIdx.x;  // b*NA + a
    int b = row >> 6, a = row & 63;
    int i = threadIdx.x;
    float acc = 0.f;
    #pragma unroll
    for (int sp = 0; sp < 8; sp++)
        acc += g_vap[(size_t)(b*8 + sp)*NA*DD + (size_t)a*DD + i];
    r0[i] = acc;
    __syncthreads();
    int o = threadIdx.x;
    float s = g_bvf[o];
    #pragma unroll 8
    for (int d = 0; d < DD; d++) s += r0[d] * g_Wvf[d*DD + o];
    g_va[(size_t)row*DD + o] = __float2bfloat16(s);
}

// ---------------- stage 2: logits(x@Ka') + dbias -> softmax -> @ va ---------
__global__ void __launch_bounds__(256) stage2() {
    extern __shared__ __align__(16) char sm2[];
    __nv_bfloat16 (*Qs)[128][40] = ( __nv_bfloat16(*)[128][40]) sm2;             // 20480
    __nv_bfloat16 (*Ka)[64][40]  = ( __nv_bfloat16(*)[64][40]) (sm2 + 20480);    // 10240
    float* logits                = ( float*)                   (sm2 + 30720);    // 34816
    __nv_bfloat16 (*Vs)[264]     = ( __nv_bfloat16(*)[264])    (sm2 + 65536);    // 33792
    __nv_bfloat16 (*Pm)[72]      = ( __nv_bfloat16(*)[72])     sm2;              // reuse Qs
    float (*epi)[16][16]         = ( float(*)[16][16])         (sm2 + 20480);    // reuse Ka
    __shared__ float dbs[NA];
    uint32_t sQ = smem_u32(sm2), sKa = sQ + 20480u, sV = sQ + 65536u;

    int b = blockIdx.y, t0 = blockIdx.x * 128;
    int tid = threadIdx.x;
    int w = tid >> 5, lane = tid & 31;

    if (tid < NA) dbs[tid] = g_dbias[tid];

    // async prefetch va tile [64,256] into Vs
    #pragma unroll
    for (int r = 0; r < 8; r++) {
        int idx = tid + r*256;
        int vr = idx >> 5, vc = (idx & 31) * 8;
        CPA16(sV + (uint32_t)vr*528u + (uint32_t)vc*2u,
              g_va + (size_t)(b*NA + vr)*DD + vc);
    }
    CPA_COMMIT();

    // --- phase A: logits[128,64] = x_tile @ Ka'^T, warps 4x2, warp 32x32 ---
    {
        int wm = w >> 1, wn = w & 1;
        wmma::fragment<wmma::accumulator,16,16,16,float> acc[2][2];
        #pragma unroll
        for (int i = 0; i < 2; i++)
            #pragma unroll
            for (int j = 0; j < 2; j++) wmma::fill_fragment(acc[i][j], 0.f);

        #define S2_STAGE(kc, bb) {                                                 \
            _Pragma("unroll")                                                      \
            for (int r = 0; r < 2; r++) {                                          \
                int idx = tid + r*256;                                             \
                int qr = idx >> 2, qc = (idx & 3) * 8;                             \
                CPA16(sQ + (uint32_t)(bb)*10240u + (uint32_t)qr*80u + (uint32_t)qc*2u, \
                      g_xb + (size_t)(b*NT + t0 + qr)*DD + (kc) + qc);             \
            }                                                                      \
            {   int ar = tid >> 2, ac = (tid & 3) * 8;                             \
                CPA16(sKa + (uint32_t)(bb)*5120u + (uint32_t)ar*80u + (uint32_t)ac*2u, \
                      g_kat + (size_t)ar*DD + (kc) + ac); }                        \
            CPA_COMMIT(); }

        S2_STAGE(0, 0);
        for (int s = 0; s < 8; s++) {
            CPA_WAIT(0);
            __syncthreads();
            if (s < 7) S2_STAGE((s+1)*32, (s+1)&1);
            int bb = s & 1;
            #pragma unroll
            for (int kk = 0; kk < 2; kk++) {
                wmma::fragment<wmma::matrix_a,16,16,16,__nv_bfloat16,wmma::row_major> af[2];
                wmma::fragment<wmma::matrix_b,16,16,16,__nv_bfloat16,wmma::col_major> bf[2];
                #pragma unroll
                for (int i = 0; i < 2; i++)
                    wmma::load_matrix_sync(af[i], &Qs[bb][wm*32 + i*16][kk*16], 40);
                #pragma unroll
                for (int j = 0; j < 2; j++)
                    wmma::load_matrix_sync(bf[j], &Ka[bb][wn*32 + j*16][kk*16], 40);
                #pragma unroll
                for (int i = 0; i < 2; i++)
                    #pragma unroll
                    for (int j = 0; j < 2; j++)
                        wmma::mma_sync(acc[i][j], af[i], bf[j], acc[i][j]);
            }
        }
        #undef S2_STAGE
        __syncthreads();
        #pragma unroll
        for (int i = 0; i < 2; i++)
            #pragma unroll
            for (int j = 0; j < 2; j++)
                wmma::store_matrix_sync(logits + (wm*32 + i*16)*68 + wn*32 + j*16,
                                        acc[i][j], 68, wmma::mem_row_major);
    }
    __syncthreads();

    // --- phase B: per-row softmax over 64 agents (+dbias) -> Pm ---
    if (tid < 128) {
        const float* lr = logits + tid*68;
        float lv[64];
        #pragma unroll 8
        for (int c = 0; c < 64; c++) lv[c] = lr[c] + dbs[c];
        float m = -1e30f;
        #pragma unroll 8
        for (int c = 0; c < 64; c++) m = fmaxf(m, lv[c]);
        float sum = 0.f;
        #pragma unroll 8
        for (int c = 0; c < 64; c++) sum += __expf(lv[c] - m);
        float inv = 1.f / sum;
        #pragma unroll 8
        for (int c = 0; c < 64; c++)
            Pm[tid][c] = __float2bfloat16(__expf(lv[c] - m) * inv);
    }
    __syncthreads();

    // --- phase C: mid[128,256] = Pm[128,64] @ Vs[64,256]; two N passes ---
    {
        int wm = w >> 1, wn = w & 1;
        for (int nc = 0; nc < 2; nc++) {
            wmma::fragment<wmma::accumulator,16,16,16,float> acc[2][4];
            #pragma unroll
            for (int i = 0; i < 2; i++)
                #pragma unroll
                for (int j = 0; j < 4; j++) wmma::fill_fragment(acc[i][j], 0.f);
            #pragma unroll
            for (int kk = 0; kk < 4; kk++) {
                wmma::fragment<wmma::matrix_a,16,16,16,__nv_bfloat16,wmma::row_major> af[2];
                wmma::fragment<wmma::matrix_b,16,16,16,__nv_bfloat16,wmma::row_major> bf[4];
                #pragma unroll
                for (int i = 0; i < 2; i++)
                    wmma::load_matrix_sync(af[i], &Pm[wm*32 + i*16][kk*16], 72);
                #pragma unroll
                for (int j = 0; j < 4; j++)
                    wmma::load_matrix_sync(bf[j], &Vs[kk*16][nc*128 + wn*64 + j*16], 264);
                #pragma unroll
                for (int i = 0; i < 2; i++)
                    #pragma unroll
                    for (int j = 0; j < 4; j++)
                        wmma::mma_sync(acc[i][j], af[i], bf[j], acc[i][j]);
            }
            int r = lane >> 1, c8 = (lane & 1) * 8;
            #pragma unroll
            for (int i = 0; i < 2; i++)
                #pragma unroll
                for (int j = 0; j < 4; j++) {
                    wmma::store_matrix_sync(&epi[w][0][0], acc[i][j], 16, wmma::mem_row_major);
                    __syncwarp();
                    int grow = t0 + wm*32 + i*16 + r;
                    int gcol = nc*128 + wn*64 + j*16 + c8;
                    __nv_bfloat16 tmp[8];
                    #pragma unroll
                    for (int e = 0; e < 8; e++)
                        tmp[e] = __float2bfloat16(epi[w][r][c8+e]);
                    *(uint4*)(g_mid + (size_t)(b*NT + grow)*DD + gcol) = *(uint4*)tmp;
                    __syncwarp();
                }
        }
    }
}

// ---------------- fc2 + bias + residual -> out ------------------------------
__global__ void __launch_bounds__(128) gemm_fc2(const float* __restrict__ bias,
                                                const float* __restrict__ x,
                                                float* __restrict__ out) {
    extern __shared__ __align__(16) char smf[];
    __nv_bfloat16 (*As)[128][72] = (__nv_bfloat16(*)[128][72]) smf;
    __nv_bfloat16 (*Bs)[64][136] = (__nv_bfloat16(*)[64][136])(smf + 36864);
    float (*epi)[16][16]         = (float(*)[16][16])          smf;
    uint32_t sA = smem_u32(smf), sB = sA + 36864u;

    int tid = threadIdx.x;
    int w = tid >> 5, lane = tid & 31;
    int wm = w >> 1, wn = w & 1;
    int row0 = blockIdx.y * 128, col0 = blockIdx.x * 128;

    wmma::fragment<wmma::accumulator,16,16,16,float> acc[4][4];
    #pragma unroll
    for (int i = 0; i < 4; i++)
        #pragma unroll
        for (int j = 0; j < 4; j++) wmma::fill_fragment(acc[i][j], 0.f);

    #define FC2_STAGE(kc, bb) {                                                    \
        _Pragma("unroll")                                                          \
        for (int r = 0; r < 8; r++) {                                              \
            int idx = tid + r*128;                                                 \
            int ar = idx >> 3, ac = (idx & 7) * 8;                                 \
            CPA16(sA + (uint32_t)(bb)*18432u + (uint32_t)ar*144u + (uint32_t)ac*2u,\
                  g_mid + (size_t)(row0+ar)*DD + (kc) + ac);                       \
        }                                                                          \
        _Pragma("unroll")                                                          \
        for (int r = 0; r < 8; r++) {                                              \
            int idx = tid + r*128;                                                 \
            int br = idx >> 4, bc = (idx & 15) * 8;                                \
            CPA16(sB + (uint32_t)(bb)*17408u + (uint32_t)br*272u + (uint32_t)bc*2u,\
                  g_Wfc2 + (size_t)((kc)+br)*DD + col0 + bc);                      \
        }                                                                          \
        CPA_COMMIT(); }

    FC2_STAGE(0, 0);
    for (int s = 0; s < 4; s++) {
        CPA_WAIT(0);
        __syncthreads();
        if (s < 3) FC2_STAGE((s+1)*64, (s+1)&1);
        int bb = s & 1;
        #pragma unroll
        for (int k4 = 0; k4 < 4; k4++) {
            wmma::fragment<wmma::matrix_a,16,16,16,__nv_bfloat16,wmma::row_major> af[4];
            wmma::fragment<wmma::matrix_b,16,16,16,__nv_bfloat16,wmma::row_major> bf[4];
            #pragma unroll
            for (int i = 0; i < 4; i++)
                wmma::load_matrix_sync(af[i], &As[bb][wm*64 + i*16][k4*16], 72);
            #pragma unroll
            for (int j = 0; j < 4; j++)
                wmma::load_matrix_sync(bf[j], &Bs[bb][k4*16][wn*64 + j*16], 136);
            #pragma unroll
            for (int i = 0; i < 4; i++)
                #pragma unroll
                for (int j = 0; j < 4; j++)
                    wmma::mma_sync(acc[i][j], af[i], bf[j], acc[i][j]);
        }
    }
    #undef FC2_STAGE
    __syncthreads();

    int r = lane >> 1, c8 = (lane & 1) * 8;
    #pragma unroll
    for (int i = 0; i < 4; i++)
        #pragma unroll
        for (int j = 0; j < 4; j++) {
            wmma::store_matrix_sync(&epi[w][0][0], acc[i][j], 16, wmma::mem_row_major);
            __syncwarp();
            int gr = row0 + wm*64 + i*16 + r;
            int gc = col0 + wn*64 + j*16 + c8;
            size_t gi = (size_t)gr*DD + gc;
            float o0[4], o1[4];
            #pragma unroll
            for (int e = 0; e < 4; e++) o0[e] = epi[w][r][c8+e]   + bias[gc+e]   + x[gi+e];
            #pragma unroll
            for (int e = 0; e < 4; e++) o1[e] = epi[w][r][c8+4+e] + bias[gc+4+e] + x[gi+4+e];
            *(float4*)(out + gi)     = *(float4*)o0;
            *(float4*)(out + gi + 4) = *(float4*)o1;
            __syncwarp();
        }
}

// ---------------- launcher ---------------------------------------------------
#define BIG_SMEM 71680

extern "C" void kernel_launch(void* const* d_in, const int* in_sizes, int n_in,
                              void* d_out, int out_size) {
    const float* agent = (const float*)d_in[0];
    const float* x     = (const float*)d_in[1];
    const float* Wqkv  = (const float*)d_in[2];
    const float* bqkv  = (const float*)d_in[3];
    const float* Wag   = (const float*)d_in[4];
    const float* bag   = (const float*)d_in[5];
    const float* Wfc1  = (const float*)d_in[6];
    const float* bfc1  = (const float*)d_in[7];
    const float* Wfc2  = (const float*)d_in[8];
    const float* bfc2  = (const float*)d_in[9];
    float* out = (float*)d_out;

    cudaFuncSetAttribute(stage2,   cudaFuncAttributeMaxDynamicSharedMemorySize, 99328);
    cudaFuncSetAttribute(gemm_fc2, cudaFuncAttributeMaxDynamicSharedMemorySize, BIG_SMEM);
    cudaFuncSetAttribute(wvf_gemm, cudaFuncAttributeMaxDynamicSharedMemorySize, BIG_SMEM);

    conv_inputs<<<2048, 256>>>(x, Wfc2, Wqkv, Wfc1);
    agent_proj<<<64, 512>>>(agent, Wag, bag);
    proj_agents<<<dim3(4, 2), 256>>>();
    wvf_gemm<<<dim3(2, 2), 128, BIG_SMEM>>>();
    dbias_k<<<64, 256>>>(bqkv);
    bvf_k<<<1, 256>>>(Wfc1, bqkv, bfc1);
    gemm_s1<<<dim3(32, 8), 256>>>();
    softmax1<<<512, 256>>>();
    gemm_va0<<<dim3(8, 8), 256>>>();
    fc1k<<<512, 256>>>();
    stage2<<<dim3(32, 8), 256, 99328>>>();
    gemm_fc2<<<dim3(2, 256), 128, BIG_SMEM>>>(bfc2, x, out);
}

// round 9
// speedup vs baseline: 1.4763x; 1.0748x over previous
#include <cuda_runtime.h>
#include <cuda_bf16.h>
#include <mma.h>
#include <cstdint>

using namespace nvcuda;

#define NB 8
#define NT 4096
#define NA 64
#define DD 256
#define MTOK (NB*NT)
#define W3 (3*DD)

// ---------------- scratch (device globals; no allocations allowed) ----------
__device__ __nv_bfloat16 g_xb[MTOK*DD];              // x in bf16
__device__ __nv_bfloat16 g_Wfc2[DD*DD];              // W_fc2 bf16 [K,N]
__device__ __nv_bfloat16 g_Wqkvb[DD*W3];             // W_qkv bf16 [K, 3N]
__device__ __nv_bfloat16 g_Wfc1b[DD*DD];             // W_fc1 bf16 [K,N]
__device__ __nv_bfloat16 g_qasb[NA*DD];              // qa_s bf16 (scale folded)
__device__ __nv_bfloat16 g_kasb[NA*DD];              // ka_s bf16 (scale folded)
__device__ float        g_kaf[NA*DD];                // ka_s fp32 (for dbias)
__device__ __nv_bfloat16 g_qap[NA*DD];               // qa' = qa_s @ Wk^T, bf16
__device__ __nv_bfloat16 g_kat[NA*DD];               // Ka' [a,i] bf16
__device__ float        g_dbias[NA];                 // bq . ka_s
__device__ __nv_bfloat16 g_Wvfb[DD*DD];              // Wv @ Wfc1, bf16
__device__ float        g_Wvf2[DD*DD];               // (Wv@Wfc1)@Wfc2, fp32
__device__ float        g_bvf[DD];                   // bv@Wfc1 + bfc1
__device__ float        g_bvf2[DD];                  // bvf @ Wfc2
__device__ float        g_S1[NB*NA*NT];              // stage-1 logits
__device__ __nv_bfloat16 g_P1[NB*NA*NT];             // stage-1 probs
__device__ float        g_vap[NB*8*NA*DD];           // split-K partials of P1@x
__device__ __nv_bfloat16 g_va[NB*NA*DD];             // u@Wvf2+bvf2, bf16

// ---------------- cp.async helpers ------------------------------------------
__device__ __forceinline__ uint32_t smem_u32(const void* p) {
    uint32_t a;
    asm("{ .reg .u64 t; cvta.to.shared.u64 t, %1; cvt.u32.u64 %0, t; }" : "=r"(a) : "l"(p));
    return a;
}
#define CPA16(s, g)  asm volatile("cp.async.cg.shared.global [%0], [%1], 16;" :: "r"(s), "l"(g))
#define CPA_COMMIT() asm volatile("cp.async.commit_group;" ::: "memory")
#define CPA_WAIT(n)  asm volatile("cp.async.wait_group %0;" :: "n"(n) : "memory")

// ---------------- input conversion (x, W_fc2, W_qkv, W_fc1) -----------------
__global__ void conv_inputs(const float* __restrict__ x,
                            const float* __restrict__ Wfc2,
                            const float* __restrict__ Wqkv,
                            const float* __restrict__ Wfc1) {
    int stride = gridDim.x * blockDim.x;
    int tid = blockIdx.x * blockDim.x + threadIdx.x;
    for (int i = tid; i < (MTOK*DD)/4; i += stride) {
        float4 v = *(const float4*)(x + i*4);
        __nv_bfloat16 t[4] = {__float2bfloat16(v.x), __float2bfloat16(v.y),
                              __float2bfloat16(v.z), __float2bfloat16(v.w)};
        *(uint2*)(g_xb + i*4) = *(uint2*)t;
    }
    for (int i = tid; i < DD*DD; i += stride)
        g_Wfc2[i] = __float2bfloat16(Wfc2[i]);
    for (int i = tid; i < DD*W3; i += stride)
        g_Wqkvb[i] = __float2bfloat16(Wqkv[i]);
    for (int i = tid; i < DD*DD; i += stride)
        g_Wfc1b[i] = __float2bfloat16(Wfc1[i]);
}

// ---------------- agent projection (scale folded) ---------------------------
__global__ void agent_proj(const float* __restrict__ agent,
                           const float* __restrict__ W,
                           const float* __restrict__ b) {
    __shared__ float arow[DD];
    int a = blockIdx.x;
    for (int i = threadIdx.x; i < DD; i += blockDim.x)
        arow[i] = agent[a*DD + i];
    __syncthreads();
    int o = threadIdx.x;  // 0..511
    float s = 0.f;
    #pragma unroll 8
    for (int d = 0; d < DD; d++)
        s += arow[d] * W[d*2*DD + o];
    s += b[o];
    s *= 0.0625f;  // 256^-0.5
    if (o < DD) {
        g_qasb[a*DD + o] = __float2bfloat16(s);
    } else {
        g_kasb[a*DD + (o-DD)] = __float2bfloat16(s);
        g_kaf [a*DD + (o-DD)] = s;
    }
}

// ---------------- proj_agents (cp.async-staged WMMA) -------------------------
// sel 0: qa' = qa_s @ Wk^T ; sel 1: Ka' = ka_s @ Wq^T ; grid (4 i-tiles, 2 sel)
__global__ void __launch_bounds__(256) proj_agents() {
    __shared__ __nv_bfloat16 Aa[2][64][40];
    __shared__ __nv_bfloat16 Ws[2][64][40];
    __shared__ float epi[8][16][16];
    uint32_t sA = smem_u32(&Aa[0][0][0]);
    uint32_t sW = smem_u32(&Ws[0][0][0]);

    int sel = blockIdx.y;
    int col0 = blockIdx.x * 64;
    const __nv_bfloat16* A  = sel ? g_kasb : g_qasb;
    const __nv_bfloat16* Bb = g_Wqkvb + (sel ? 0 : DD);
    __nv_bfloat16* C = sel ? g_kat : g_qap;
    int tid = threadIdx.x;
    int w = tid >> 5, lane = tid & 31;
    int wm = w >> 2, wn = w & 3;                // 2x4, warp 32x16

    wmma::fragment<wmma::accumulator,16,16,16,float> acc[2];
    #pragma unroll
    for (int i = 0; i < 2; i++) wmma::fill_fragment(acc[i], 0.f);

    #define PA_STAGE(kc, bb) {                                                     \
        {   int ar = tid >> 2, ac = (tid & 3) * 8;                                 \
            CPA16(sA + (uint32_t)(bb)*5120u + (uint32_t)ar*80u + (uint32_t)ac*2u,  \
                  A + (size_t)ar*DD + (kc) + ac); }                                \
        {   int wr = tid >> 2, wc = (tid & 3) * 8;                                 \
            CPA16(sW + (uint32_t)(bb)*5120u + (uint32_t)wr*80u + (uint32_t)wc*2u,  \
                  Bb + (size_t)(col0 + wr)*W3 + (kc) + wc); }                      \
        CPA_COMMIT(); }

    PA_STAGE(0, 0);
    for (int s = 0; s < 8; s++) {
        CPA_WAIT(0);
        __syncthreads();
        if (s < 7) PA_STAGE((s+1)*32, (s+1)&1);
        int bb = s & 1;
        #pragma unroll
        for (int kk = 0; kk < 2; kk++) {
            wmma::fragment<wmma::matrix_a,16,16,16,__nv_bfloat16,wmma::row_major> af[2];
            wmma::fragment<wmma::matrix_b,16,16,16,__nv_bfloat16,wmma::col_major> bf;
            #pragma unroll
            for (int i = 0; i < 2; i++)
                wmma::load_matrix_sync(af[i], &Aa[bb][wm*32 + i*16][kk*16], 40);
            wmma::load_matrix_sync(bf, &Ws[bb][wn*16][kk*16], 40);
            #pragma unroll
            for (int i = 0; i < 2; i++)
                wmma::mma_sync(acc[i], af[i], bf, acc[i]);
        }
    }
    #undef PA_STAGE

    #pragma unroll
    for (int i = 0; i < 2; i++) {
        wmma::store_matrix_sync(&epi[w][0][0], acc[i], 16, wmma::mem_row_major);
        __syncwarp();
        if (lane < 16) {
            int a = wm*32 + i*16 + lane;
            __nv_bfloat16 t8[8];
            #pragma unroll
            for (int g = 0; g < 2; g++) {
                #pragma unroll
                for (int e = 0; e < 8; e++)
                    t8[e] = __float2bfloat16(epi[w][lane][g*8+e]);
                *(uint4*)(C + (size_t)a*DD + col0 + wn*16 + g*8) = *(uint4*)t8;
            }
        }
        __syncwarp();
    }
}

// ---------------- 256x256x256 weight GEMMs, 64x64 tiles, grid (4,4) ---------
// sel 0: g_Wvfb(bf16) = Wv @ Wfc1   (A = g_Wqkvb+2*DD, lda=W3; B = g_Wfc1b)
// sel 1: g_Wvf2(f32)  = Wvfb @ Wfc2 (A = g_Wvfb, lda=DD;     B = g_Wfc2)
__global__ void __launch_bounds__(256) w64_gemm(int sel) {
    __shared__ __nv_bfloat16 As[2][64][72];
    __shared__ __nv_bfloat16 Bs[2][64][72];
    __shared__ float epi[8][16][16];
    uint32_t sA = smem_u32(&As[0][0][0]);
    uint32_t sB = smem_u32(&Bs[0][0][0]);

    int row0 = blockIdx.y * 64, col0 = blockIdx.x * 64;
    const __nv_bfloat16* A = sel ? g_Wvfb : (g_Wqkvb + 2*DD);
    int lda = sel ? DD : W3;
    const __nv_bfloat16* B = sel ? g_Wfc2 : g_Wfc1b;
    int tid = threadIdx.x, w = tid >> 5, lane = tid & 31;
    int wm = w >> 2, wn = w & 3;                 // warp 32x16

    wmma::fragment<wmma::accumulator,16,16,16,float> acc[2];
    #pragma unroll
    for (int i = 0; i < 2; i++) wmma::fill_fragment(acc[i], 0.f);

    #define W64_STAGE(kc, bb) {                                                    \
        _Pragma("unroll")                                                          \
        for (int r = 0; r < 2; r++) {                                              \
            int idx = tid + r*256;                                                 \
            int ar = idx >> 3, ac = (idx & 7) * 8;                                 \
            CPA16(sA + (uint32_t)(bb)*9216u + (uint32_t)ar*144u + (uint32_t)ac*2u, \
                  A + (size_t)(row0+ar)*lda + (kc) + ac);                          \
        }                                                                          \
        _Pragma("unroll")                                                          \
        for (int r = 0; r < 2; r++) {                                              \
            int idx = tid + r*256;                                                 \
            int br = idx >> 3, bc = (idx & 7) * 8;                                 \
            CPA16(sB + (uint32_t)(bb)*9216u + (uint32_t)br*144u + (uint32_t)bc*2u, \
                  B + (size_t)((kc)+br)*DD + col0 + bc);                           \
        }                                                                          \
        CPA_COMMIT(); }

    W64_STAGE(0, 0);
    for (int s = 0; s < 4; s++) {
        CPA_WAIT(0);
        __syncthreads();
        if (s < 3) W64_STAGE((s+1)*64, (s+1)&1);
        int bb = s & 1;
        #pragma unroll
        for (int k4 = 0; k4 < 4; k4++) {
            wmma::fragment<wmma::matrix_a,16,16,16,__nv_bfloat16,wmma::row_major> af[2];
            wmma::fragment<wmma::matrix_b,16,16,16,__nv_bfloat16,wmma::row_major> bf;
            #pragma unroll
            for (int i = 0; i < 2; i++)
                wmma::load_matrix_sync(af[i], &As[bb][wm*32 + i*16][k4*16], 72);
            wmma::load_matrix_sync(bf, &Bs[bb][k4*16][wn*16], 72);
            #pragma unroll
            for (int i = 0; i < 2; i++)
                wmma::mma_sync(acc[i], af[i], bf, acc[i]);
        }
    }
    #undef W64_STAGE
    __syncthreads();

    int r = lane >> 1, c8 = (lane & 1) * 8;
    #pragma unroll
    for (int i = 0; i < 2; i++) {
        wmma::store_matrix_sync(&epi[w][0][0], acc[i], 16, wmma::mem_row_major);
        __syncwarp();
        int gr = row0 + wm*32 + i*16 + r;
        int gc = col0 + wn*16 + c8;
        if (sel) {
            *(float4*)(g_Wvf2 + (size_t)gr*DD + gc)     = *(float4*)(&epi[w][r][c8]);
            *(float4*)(g_Wvf2 + (size_t)gr*DD + gc + 4) = *(float4*)(&epi[w][r][c8+4]);
        } else {
            __nv_bfloat16 t8[8];
            #pragma unroll
            for (int e = 0; e < 8; e++)
                t8[e] = __float2bfloat16(epi[w][r][c8+e]);
            *(uint4*)(g_Wvfb + (size_t)gr*DD + gc) = *(uint4*)t8;
        }
        __syncwarp();
    }
}

// ---------------- dbias, bvf, bvf2 ------------------------------------------
__global__ void dbias_k(const float* __restrict__ bqkv) {
    __shared__ float red[256];
    int a = blockIdx.x, i = threadIdx.x;
    red[i] = bqkv[i] * g_kaf[a*DD + i];
    __syncthreads();
    for (int st = 128; st > 0; st >>= 1) {
        if (i < st) red[i] += red[i + st];
        __syncthreads();
    }
    if (i == 0) g_dbias[a] = red[0];
}
__global__ void bvf_k(const float* __restrict__ Wfc1,
                      const float* __restrict__ bqkv, const float* __restrict__ bfc1) {
    int j = threadIdx.x;
    float t = bfc1[j];
    #pragma unroll 8
    for (int o = 0; o < DD; o++)
        t += bqkv[2*DD + o] * Wfc1[o*DD + j];
    g_bvf[j] = t;
}
__global__ void bvf2_k(const float* __restrict__ Wfc2) {
    int j = threadIdx.x;
    float t = 0.f;
    #pragma unroll 8
    for (int o = 0; o < DD; o++)
        t += g_bvf[o] * Wfc2[o*DD + j];
    g_bvf2[j] = t;
}

// ---------------- stage-1 logits: S1[b] = qa' @ x_b^T -----------------------
__global__ void __launch_bounds__(256) gemm_s1() {
    __shared__ __nv_bfloat16 Qa[2][64][40];
    __shared__ __nv_bfloat16 Ks[2][128][40];
    __shared__ float epi[8][16][16];
    uint32_t sQ = smem_u32(&Qa[0][0][0]);
    uint32_t sK = smem_u32(&Ks[0][0][0]);

    int b = blockIdx.y;
    int col0 = blockIdx.x * 128;
    int tid = threadIdx.x;
    int w = tid >> 5, lane = tid & 31;
    int wm = w >> 2, wn = w & 3;

    wmma::fragment<wmma::accumulator,16,16,16,float> acc[2][2];
    #pragma unroll
    for (int i = 0; i < 2; i++)
        #pragma unroll
        for (int j = 0; j < 2; j++) wmma::fill_fragment(acc[i][j], 0.f);

    #define S1_STAGE(kc, bb) {                                                     \
        {   int ar = tid >> 2, ac = (tid & 3) * 8;                                 \
            CPA16(sQ + (uint32_t)(bb)*5120u + (uint32_t)ar*80u + (uint32_t)ac*2u,  \
                  g_qap + (size_t)ar*DD + (kc) + ac); }                            \
        _Pragma("unroll")                                                          \
        for (int r = 0; r < 2; r++) {                                              \
            int idx = tid + r*256;                                                 \
            int kr = idx >> 2, kcc = (idx & 3) * 8;                                \
            CPA16(sK + (uint32_t)(bb)*10240u + (uint32_t)kr*80u + (uint32_t)kcc*2u,\
                  g_xb + (size_t)(b*NT + col0 + kr)*DD + (kc) + kcc);              \
        }                                                                          \
        CPA_COMMIT(); }

    S1_STAGE(0, 0);
    for (int s = 0; s < 8; s++) {
        CPA_WAIT(0);
        __syncthreads();
        if (s < 7) S1_STAGE((s+1)*32, (s+1)&1);
        int bb = s & 1;
        #pragma unroll
        for (int kk = 0; kk < 2; kk++) {
            wmma::fragment<wmma::matrix_a,16,16,16,__nv_bfloat16,wmma::row_major> af[2];
            wmma::fragment<wmma::matrix_b,16,16,16,__nv_bfloat16,wmma::col_major> bf[2];
            #pragma unroll
            for (int i = 0; i < 2; i++)
                wmma::load_matrix_sync(af[i], &Qa[bb][wm*32 + i*16][kk*16], 40);
            #pragma unroll
            for (int j = 0; j < 2; j++)
                wmma::load_matrix_sync(bf[j], &Ks[bb][wn*32 + j*16][kk*16], 40);
            #pragma unroll
            for (int i = 0; i < 2; i++)
                #pragma unroll
                for (int j = 0; j < 2; j++)
                    wmma::mma_sync(acc[i][j], af[i], bf[j], acc[i][j]);
        }
    }
    #undef S1_STAGE

    float* outb = g_S1 + (size_t)b*NA*NT;
    #pragma unroll
    for (int i = 0; i < 2; i++)
        #pragma unroll
        for (int j = 0; j < 2; j++) {
            wmma::store_matrix_sync(&epi[w][0][0], acc[i][j], 16, wmma::mem_row_major);
            __syncwarp();
            #pragma unroll
            for (int e = 0; e < 2; e++) {
                int idx2 = lane + e*32;
                int r = idx2 >> 2, c4 = (idx2 & 3) * 4;
                int ga = wm*32 + i*16 + r;
                int gt = col0 + wn*32 + j*16 + c4;
                *(float4*)(outb + (size_t)ga*NT + gt) = *(float4*)(&epi[w][r][c4]);
            }
            __syncwarp();
        }
}

// ---------------- stage-1 softmax over N=4096 (smem row cache) --------------
__global__ void softmax1() {
    __shared__ float rowc[NT];
    __shared__ float red[8];
    int row = blockIdx.x;
    const float* s = g_S1 + (size_t)row*NT;
    __nv_bfloat16* p = g_P1 + (size_t)row*NT;
    int t = threadIdx.x;

    float m = -1e30f;
    for (int i = t; i < NT/4; i += 256) {
        float4 v = *(const float4*)(s + i*4);
        *(float4*)(rowc + i*4) = v;
        m = fmaxf(fmaxf(m, fmaxf(v.x, v.y)), fmaxf(v.z, v.w));
    }
    #pragma unroll
    for (int o = 16; o; o >>= 1) m = fmaxf(m, __shfl_xor_sync(0xffffffffu, m, o));
    if ((t & 31) == 0) red[t >> 5] = m;
    __syncthreads();
    float gm = red[0];
    #pragma unroll
    for (int i = 1; i < 8; i++) gm = fmaxf(gm, red[i]);
    __syncthreads();

    float sum = 0.f;
    for (int i = t; i < NT; i += 256) sum += __expf(rowc[i] - gm);
    #pragma unroll
    for (int o = 16; o; o >>= 1) sum += __shfl_xor_sync(0xffffffffu, sum, o);
    if ((t & 31) == 0) red[t >> 5] = sum;
    __syncthreads();
    float gs = 0.f;
    #pragma unroll
    for (int i = 0; i < 8; i++) gs += red[i];
    float inv = 1.f / gs;
    for (int i = t; i < NT/4; i += 256) {
        float4 v = *(const float4*)(rowc + i*4);
        __nv_bfloat16 t4[4] = {
            __float2bfloat16(__expf(v.x - gm) * inv),
            __float2bfloat16(__expf(v.y - gm) * inv),
            __float2bfloat16(__expf(v.z - gm) * inv),
            __float2bfloat16(__expf(v.w - gm) * inv)};
        *(uint2*)(p + i*4) = *(uint2*)t4;
    }
}

// ---------------- u partials: split-K over tokens (u = P1 @ x) ---------------
__global__ void __launch_bounds__(256) gemm_va0() {
    __shared__ __align__(16) char smva[44032];
    __nv_bfloat16 (*Ps)[64][40]  = ( __nv_bfloat16(*)[64][40])  smva;          // 2x5120
    __nv_bfloat16 (*Vs)[32][264] = ( __nv_bfloat16(*)[32][264])(smva + 10240); // 2x16896
    float (*epi)[16][16]         = ( float(*)[16][16])          smva;          // reuse Ps
    uint32_t sP = smem_u32(smva), sV = sP + 10240u;

    int split = blockIdx.x, b = blockIdx.y;
    int tok0 = split * 512;
    int tid = threadIdx.x;
    int w = tid >> 5, lane = tid & 31;
    int wm = w >> 2, wn = w & 3;

    wmma::fragment<wmma::accumulator,16,16,16,float> acc[2][4];
    #pragma unroll
    for (int i = 0; i < 2; i++)
        #pragma unroll
        for (int j = 0; j < 4; j++) wmma::fill_fragment(acc[i][j], 0.f);

    #define VA_STAGE(kc, bb) {                                                     \
        {   int pr = tid >> 2, pc = (tid & 3) * 8;                                 \
            CPA16(sP + (uint32_t)(bb)*5120u + (uint32_t)pr*80u + (uint32_t)pc*2u,  \
                  g_P1 + (size_t)b*NA*NT + (size_t)pr*NT + tok0 + (kc) + pc); }    \
        _Pragma("unroll")                                                          \
        for (int r = 0; r < 4; r++) {                                              \
            int idx = tid + r*256;                                                 \
            int vr = idx >> 5, vc = (idx & 31) * 8;                                \
            CPA16(sV + (uint32_t)(bb)*16896u + (uint32_t)vr*528u + (uint32_t)vc*2u,\
                  g_xb + (size_t)(b*NT + tok0 + (kc) + vr)*DD + vc);               \
        }                                                                          \
        CPA_COMMIT(); }

    VA_STAGE(0, 0);
    for (int s = 0; s < 16; s++) {
        CPA_WAIT(0);
        __syncthreads();
        if (s < 15) VA_STAGE((s+1)*32, (s+1)&1);
        int bb = s & 1;
        #pragma unroll
        for (int kk = 0; kk < 2; kk++) {
            wmma::fragment<wmma::matrix_a,16,16,16,__nv_bfloat16,wmma::row_major> af[2];
            wmma::fragment<wmma::matrix_b,16,16,16,__nv_bfloat16,wmma::row_major> bf[4];
            #pragma unroll
            for (int i = 0; i < 2; i++)
                wmma::load_matrix_sync(af[i], &Ps[bb][wm*32 + i*16][kk*16], 40);
            #pragma unroll
            for (int j = 0; j < 4; j++)
                wmma::load_matrix_sync(bf[j], &Vs[bb][kk*16][wn*64 + j*16], 264);
            #pragma unroll
            for (int i = 0; i < 2; i++)
                #pragma unroll
                for (int j = 0; j < 4; j++)
                    wmma::mma_sync(acc[i][j], af[i], bf[j], acc[i][j]);
        }
    }
    #undef VA_STAGE
    __syncthreads();

    float* outb = g_vap + (size_t)(b*8 + split)*NA*DD;
    #pragma unroll
    for (int i = 0; i < 2; i++)
        #pragma unroll
        for (int j = 0; j < 4; j++) {
            wmma::store_matrix_sync(&epi[w][0][0], acc[i][j], 16, wmma::mem_row_major);
            __syncwarp();
            #pragma unroll
            for (int e = 0; e < 2; e++) {
                int idx2 = lane + e*32;
                int r = idx2 >> 2, c4 = (idx2 & 3) * 4;
                int ga = wm*32 + i*16 + r;
                int gd = wn*64 + j*16 + c4;
                *(float4*)(outb + (size_t)ga*DD + gd) = *(float4*)(&epi[w][r][c4]);
            }
            __syncwarp();
        }
}

// ---------------- fc1: sum partials, then va2 = u @ Wvf2 + bvf2 -------------
__global__ void fc1k() {
    __shared__ float r0[DD];
    int row = blockIdx.x;  // b*NA + a
    int b = row >> 6, a = row & 63;
    int i = threadIdx.x;
    float acc = 0.f;
    #pragma unroll
    for (int sp = 0; sp < 8; sp++)
        acc += g_vap[(size_t)(b*8 + sp)*NA*DD + (size_t)a*DD + i];
    r0[i] = acc;
    __syncthreads();
    int o = threadIdx.x;
    float s = g_bvf2[o];
    #pragma unroll 8
    for (int d = 0; d < DD; d++) s += r0[d] * g_Wvf2[d*DD + o];
    g_va[(size_t)row*DD + o] = __float2bfloat16(s);
}

// ---------------- stage 2 fused: logits -> softmax -> P@va2 + bfc2 + x -------
__global__ void __launch_bounds__(256) stage2(const float* __restrict__ bfc2,
                                              const float* __restrict__ x,
                                              float* __restrict__ out) {
    extern __shared__ __align__(16) char sm2[];
    __nv_bfloat16 (*Qs)[128][40] = ( __nv_bfloat16(*)[128][40]) sm2;             // 20480
    __nv_bfloat16 (*Ka)[64][40]  = ( __nv_bfloat16(*)[64][40]) (sm2 + 20480);    // 10240
    float* logits                = ( float*)                   (sm2 + 30720);    // 34816
    __nv_bfloat16 (*Vs)[264]     = ( __nv_bfloat16(*)[264])    (sm2 + 65536);    // 33792
    __nv_bfloat16 (*Pm)[72]      = ( __nv_bfloat16(*)[72])     sm2;              // reuse Qs
    float (*epi)[16][16]         = ( float(*)[16][16])         (sm2 + 20480);    // reuse Ka
    __shared__ float dbs[NA];
    uint32_t sQ = smem_u32(sm2), sKa = sQ + 20480u, sV = sQ + 65536u;

    int b = blockIdx.y, t0 = blockIdx.x * 128;
    int tid = threadIdx.x;
    int w = tid >> 5, lane = tid & 31;

    if (tid < NA) dbs[tid] = g_dbias[tid];

    // async prefetch va2 tile [64,256] into Vs
    #pragma unroll
    for (int r = 0; r < 8; r++) {
        int idx = tid + r*256;
        int vr = idx >> 5, vc = (idx & 31) * 8;
        CPA16(sV + (uint32_t)vr*528u + (uint32_t)vc*2u,
              g_va + (size_t)(b*NA + vr)*DD + vc);
    }
    CPA_COMMIT();

    // --- phase A: logits[128,64] = x_tile @ Ka'^T ---
    {
        int wm = w >> 1, wn = w & 1;
        wmma::fragment<wmma::accumulator,16,16,16,float> acc[2][2];
        #pragma unroll
        for (int i = 0; i < 2; i++)
            #pragma unroll
            for (int j = 0; j < 2; j++) wmma::fill_fragment(acc[i][j], 0.f);

        #define S2_STAGE(kc, bb) {                                                 \
            _Pragma("unroll")                                                      \
            for (int r = 0; r < 2; r++) {                                          \
                int idx = tid + r*256;                                             \
                int qr = idx >> 2, qc = (idx & 3) * 8;                             \
                CPA16(sQ + (uint32_t)(bb)*10240u + (uint32_t)qr*80u + (uint32_t)qc*2u, \
                      g_xb + (size_t)(b*NT + t0 + qr)*DD + (kc) + qc);             \
            }                                                                      \
            {   int ar = tid >> 2, ac = (tid & 3) * 8;                             \
                CPA16(sKa + (uint32_t)(bb)*5120u + (uint32_t)ar*80u + (uint32_t)ac*2u, \
                      g_kat + (size_t)ar*DD + (kc) + ac); }                        \
            CPA_COMMIT(); }

        S2_STAGE(0, 0);
        for (int s = 0; s < 8; s++) {
            CPA_WAIT(0);
            __syncthreads();
            if (s < 7) S2_STAGE((s+1)*32, (s+1)&1);
            int bb = s & 1;
            #pragma unroll
            for (int kk = 0; kk < 2; kk++) {
                wmma::fragment<wmma::matrix_a,16,16,16,__nv_bfloat16,wmma::row_major> af[2];
                wmma::fragment<wmma::matrix_b,16,16,16,__nv_bfloat16,wmma::col_major> bf[2];
                #pragma unroll
                for (int i = 0; i < 2; i++)
                    wmma::load_matrix_sync(af[i], &Qs[bb][wm*32 + i*16][kk*16], 40);
                #pragma unroll
                for (int j = 0; j < 2; j++)
                    wmma::load_matrix_sync(bf[j], &Ka[bb][wn*32 + j*16][kk*16], 40);
                #pragma unroll
                for (int i = 0; i < 2; i++)
                    #pragma unroll
                    for (int j = 0; j < 2; j++)
                        wmma::mma_sync(acc[i][j], af[i], bf[j], acc[i][j]);
            }
        }
        #undef S2_STAGE
        __syncthreads();
        #pragma unroll
        for (int i = 0; i < 2; i++)
            #pragma unroll
            for (int j = 0; j < 2; j++)
                wmma::store_matrix_sync(logits + (wm*32 + i*16)*68 + wn*32 + j*16,
                                        acc[i][j], 68, wmma::mem_row_major);
    }
    __syncthreads();

    // --- phase B: per-row softmax over 64 agents (+dbias) -> Pm ---
    if (tid < 128) {
        const float* lr = logits + tid*68;
        float lv[64];
        #pragma unroll 8
        for (int c = 0; c < 64; c++) lv[c] = lr[c] + dbs[c];
        float m = -1e30f;
        #pragma unroll 8
        for (int c = 0; c < 64; c++) m = fmaxf(m, lv[c]);
        float sum = 0.f;
        #pragma unroll 8
        for (int c = 0; c < 64; c++) sum += __expf(lv[c] - m);
        float inv = 1.f / sum;
        #pragma unroll 8
        for (int c = 0; c < 64; c++)
            Pm[tid][c] = __float2bfloat16(__expf(lv[c] - m) * inv);
    }
    __syncthreads();

    // --- phase C: out[128,256] = Pm[128,64] @ Vs[64,256] + bfc2 + x ---
    {
        int wm = w >> 1, wn = w & 1;
        for (int nc = 0; nc < 2; nc++) {
            wmma::fragment<wmma::accumulator,16,16,16,float> acc[2][4];
            #pragma unroll
            for (int i = 0; i < 2; i++)
                #pragma unroll
                for (int j = 0; j < 4; j++) wmma::fill_fragment(acc[i][j], 0.f);
            #pragma unroll
            for (int kk = 0; kk < 4; kk++) {
                wmma::fragment<wmma::matrix_a,16,16,16,__nv_bfloat16,wmma::row_major> af[2];
                wmma::fragment<wmma::matrix_b,16,16,16,__nv_bfloat16,wmma::row_major> bf[4];
                #pragma unroll
                for (int i = 0; i < 2; i++)
                    wmma::load_matrix_sync(af[i], &Pm[wm*32 + i*16][kk*16], 72);
                #pragma unroll
                for (int j = 0; j < 4; j++)
                    wmma::load_matrix_sync(bf[j], &Vs[kk*16][nc*128 + wn*64 + j*16], 264);
                #pragma unroll
                for (int i = 0; i < 2; i++)
                    #pragma unroll
                    for (int j = 0; j < 4; j++)
                        wmma::mma_sync(acc[i][j], af[i], bf[j], acc[i][j]);
            }
            int r = lane >> 1, c8 = (lane & 1) * 8;
            #pragma unroll
            for (int i = 0; i < 2; i++)
                #pragma unroll
                for (int j = 0; j < 4; j++) {
                    wmma::store_matrix_sync(&epi[w][0][0], acc[i][j], 16, wmma::mem_row_major);
                    __syncwarp();
                    int grow = t0 + wm*32 + i*16 + r;
                    int gcol = nc*128 + wn*64 + j*16 + c8;
                    size_t gi = (size_t)(b*NT + grow)*DD + gcol;
                    float o0[4], o1[4];
                    #pragma unroll
                    for (int e = 0; e < 4; e++)
                        o0[e] = epi[w][r][c8+e]   + bfc2[gcol+e]   + x[gi+e];
                    #pragma unroll
                    for (int e = 0; e < 4; e++)
                        o1[e] = epi[w][r][c8+4+e] + bfc2[gcol+4+e] + x[gi+4+e];
                    *(float4*)(out + gi)     = *(float4*)o0;
                    *(float4*)(out + gi + 4) = *(float4*)o1;
                    __syncwarp();
                }
        }
    }
}

// ---------------- launcher ---------------------------------------------------
extern "C" void kernel_launch(void* const* d_in, const int* in_sizes, int n_in,
                              void* d_out, int out_size) {
    const float* agent = (const float*)d_in[0];
    const float* x     = (const float*)d_in[1];
    const float* Wqkv  = (const float*)d_in[2];
    const float* bqkv  = (const float*)d_in[3];
    const float* Wag   = (const float*)d_in[4];
    const float* bag   = (const float*)d_in[5];
    const float* Wfc1  = (const float*)d_in[6];
    const float* bfc1  = (const float*)d_in[7];
    const float* Wfc2  = (const float*)d_in[8];
    const float* bfc2  = (const float*)d_in[9];
    float* out = (float*)d_out;

    cudaFuncSetAttribute(stage2, cudaFuncAttributeMaxDynamicSharedMemorySize, 99328);

    conv_inputs<<<2048, 256>>>(x, Wfc2, Wqkv, Wfc1);
    agent_proj<<<64, 512>>>(agent, Wag, bag);
    proj_agents<<<dim3(4, 2), 256>>>();
    w64_gemm<<<dim3(4, 4), 256>>>(0);   // Wvfb = Wv @ Wfc1 (bf16)
    w64_gemm<<<dim3(4, 4), 256>>>(1);   // Wvf2 = Wvfb @ Wfc2 (f32)
    dbias_k<<<64, 256>>>(bqkv);
    bvf_k<<<1, 256>>>(Wfc1, bqkv, bfc1);
    bvf2_k<<<1, 256>>>(Wfc2);
    gemm_s1<<<dim3(32, 8), 256>>>();
    softmax1<<<512, 256>>>();
    gemm_va0<<<dim3(8, 8), 256>>>();
    fc1k<<<512, 256>>>();
    stage2<<<dim3(32, 8), 256, 99328>>>(bfc2, x, out);
}

// round 10
// speedup vs baseline: 1.5806x; 1.0706x over previous
#include <cuda_runtime.h>
#include <cuda_bf16.h>
#include <mma.h>
#include <cstdint>

using namespace nvcuda;

#define NB 8
#define NT 4096
#define NA 64
#define DD 256
#define MTOK (NB*NT)
#define W3 (3*DD)
#define SPL 16
#define TSPL 256   // tokens per split

// ---------------- scratch (device globals; no allocations allowed) ----------
__device__ __nv_bfloat16 g_xb[MTOK*DD];              // x in bf16
__device__ __nv_bfloat16 g_Wfc2[DD*DD];              // W_fc2 bf16 [K,N]
__device__ __nv_bfloat16 g_Wqkvb[DD*W3];             // W_qkv bf16 [K, 3N]
__device__ __nv_bfloat16 g_Wfc1b[DD*DD];             // W_fc1 bf16 [K,N]
__device__ __nv_bfloat16 g_qasb[NA*DD];              // qa_s bf16 (scale folded)
__device__ __nv_bfloat16 g_kasb[NA*DD];              // ka_s bf16 (scale folded)
__device__ float        g_kaf[NA*DD];                // ka_s fp32 (for dbias)
__device__ __nv_bfloat16 g_qap[NA*DD];               // qa' = qa_s @ Wk^T, bf16
__device__ __nv_bfloat16 g_kat[NA*DD];               // Ka' [a,i] bf16
__device__ float        g_dbias[NA];                 // bq . ka_s
__device__ __nv_bfloat16 g_Wvfb[DD*DD];              // Wv @ Wfc1, bf16
__device__ float        g_Wvf2[DD*DD];               // (Wv@Wfc1)@Wfc2, fp32
__device__ float        g_bvf[DD];                   // bv@Wfc1 + bfc1
__device__ float        g_bvf2[DD];                  // bvf @ Wfc2
__device__ float        g_vap[NB*SPL*NA*DD];         // unnormalized split partials
__device__ float2       g_stats[NB*SPL*NA];          // (m_s, s_s) per split-row
__device__ __nv_bfloat16 g_va[NB*NA*DD];             // va2 bf16

// ---------------- cp.async helpers ------------------------------------------
__device__ __forceinline__ uint32_t smem_u32(const void* p) {
    uint32_t a;
    asm("{ .reg .u64 t; cvta.to.shared.u64 t, %1; cvt.u32.u64 %0, t; }" : "=r"(a) : "l"(p));
    return a;
}
#define CPA16(s, g)  asm volatile("cp.async.cg.shared.global [%0], [%1], 16;" :: "r"(s), "l"(g))
#define CPA_COMMIT() asm volatile("cp.async.commit_group;" ::: "memory")
#define CPA_WAIT(n)  asm volatile("cp.async.wait_group %0;" :: "n"(n) : "memory")

// ---------------- input conversion (x, W_fc2, W_qkv, W_fc1) -----------------
__global__ void conv_inputs(const float* __restrict__ x,
                            const float* __restrict__ Wfc2,
                            const float* __restrict__ Wqkv,
                            const float* __restrict__ Wfc1) {
    int stride = gridDim.x * blockDim.x;
    int tid = blockIdx.x * blockDim.x + threadIdx.x;
    for (int i = tid; i < (MTOK*DD)/4; i += stride) {
        float4 v = *(const float4*)(x + i*4);
        __nv_bfloat16 t[4] = {__float2bfloat16(v.x), __float2bfloat16(v.y),
                              __float2bfloat16(v.z), __float2bfloat16(v.w)};
        *(uint2*)(g_xb + i*4) = *(uint2*)t;
    }
    for (int i = tid; i < DD*DD; i += stride)
        g_Wfc2[i] = __float2bfloat16(Wfc2[i]);
    for (int i = tid; i < DD*W3; i += stride)
        g_Wqkvb[i] = __float2bfloat16(Wqkv[i]);
    for (int i = tid; i < DD*DD; i += stride)
        g_Wfc1b[i] = __float2bfloat16(Wfc1[i]);
}

// ---------------- agent projection (scale folded) ---------------------------
__global__ void agent_proj(const float* __restrict__ agent,
                           const float* __restrict__ W,
                           const float* __restrict__ b) {
    __shared__ float arow[DD];
    int a = blockIdx.x;
    for (int i = threadIdx.x; i < DD; i += blockDim.x)
        arow[i] = agent[a*DD + i];
    __syncthreads();
    int o = threadIdx.x;  // 0..511
    float s = 0.f;
    #pragma unroll 8
    for (int d = 0; d < DD; d++)
        s += arow[d] * W[d*2*DD + o];
    s += b[o];
    s *= 0.0625f;  // 256^-0.5
    if (o < DD) {
        g_qasb[a*DD + o] = __float2bfloat16(s);
    } else {
        g_kasb[a*DD + (o-DD)] = __float2bfloat16(s);
        g_kaf [a*DD + (o-DD)] = s;
    }
}

// ---------------- proj_agents (cp.async-staged WMMA) -------------------------
__global__ void __launch_bounds__(256) proj_agents() {
    __shared__ __nv_bfloat16 Aa[2][64][40];
    __shared__ __nv_bfloat16 Ws[2][64][40];
    __shared__ float epi[8][16][16];
    uint32_t sA = smem_u32(&Aa[0][0][0]);
    uint32_t sW = smem_u32(&Ws[0][0][0]);

    int sel = blockIdx.y;
    int col0 = blockIdx.x * 64;
    const __nv_bfloat16* A  = sel ? g_kasb : g_qasb;
    const __nv_bfloat16* Bb = g_Wqkvb + (sel ? 0 : DD);
    __nv_bfloat16* C = sel ? g_kat : g_qap;
    int tid = threadIdx.x;
    int w = tid >> 5, lane = tid & 31;
    int wm = w >> 2, wn = w & 3;

    wmma::fragment<wmma::accumulator,16,16,16,float> acc[2];
    #pragma unroll
    for (int i = 0; i < 2; i++) wmma::fill_fragment(acc[i], 0.f);

    #define PA_STAGE(kc, bb) {                                                     \
        {   int ar = tid >> 2, ac = (tid & 3) * 8;                                 \
            CPA16(sA + (uint32_t)(bb)*5120u + (uint32_t)ar*80u + (uint32_t)ac*2u,  \
                  A + (size_t)ar*DD + (kc) + ac); }                                \
        {   int wr = tid >> 2, wc = (tid & 3) * 8;                                 \
            CPA16(sW + (uint32_t)(bb)*5120u + (uint32_t)wr*80u + (uint32_t)wc*2u,  \
                  Bb + (size_t)(col0 + wr)*W3 + (kc) + wc); }                      \
        CPA_COMMIT(); }

    PA_STAGE(0, 0);
    for (int s = 0; s < 8; s++) {
        CPA_WAIT(0);
        __syncthreads();
        if (s < 7) PA_STAGE((s+1)*32, (s+1)&1);
        int bb = s & 1;
        #pragma unroll
        for (int kk = 0; kk < 2; kk++) {
            wmma::fragment<wmma::matrix_a,16,16,16,__nv_bfloat16,wmma::row_major> af[2];
            wmma::fragment<wmma::matrix_b,16,16,16,__nv_bfloat16,wmma::col_major> bf;
            #pragma unroll
            for (int i = 0; i < 2; i++)
                wmma::load_matrix_sync(af[i], &Aa[bb][wm*32 + i*16][kk*16], 40);
            wmma::load_matrix_sync(bf, &Ws[bb][wn*16][kk*16], 40);
            #pragma unroll
            for (int i = 0; i < 2; i++)
                wmma::mma_sync(acc[i], af[i], bf, acc[i]);
        }
    }
    #undef PA_STAGE

    #pragma unroll
    for (int i = 0; i < 2; i++) {
        wmma::store_matrix_sync(&epi[w][0][0], acc[i], 16, wmma::mem_row_major);
        __syncwarp();
        if (lane < 16) {
            int a = wm*32 + i*16 + lane;
            __nv_bfloat16 t8[8];
            #pragma unroll
            for (int g = 0; g < 2; g++) {
                #pragma unroll
                for (int e = 0; e < 8; e++)
                    t8[e] = __float2bfloat16(epi[w][lane][g*8+e]);
                *(uint4*)(C + (size_t)a*DD + col0 + wn*16 + g*8) = *(uint4*)t8;
            }
        }
        __syncwarp();
    }
}

// ---------------- 256x256x256 weight GEMMs, 64x64 tiles, grid (4,4) ---------
__global__ void __launch_bounds__(256) w64_gemm(int sel) {
    __shared__ __nv_bfloat16 As[2][64][72];
    __shared__ __nv_bfloat16 Bs[2][64][72];
    __shared__ float epi[8][16][16];
    uint32_t sA = smem_u32(&As[0][0][0]);
    uint32_t sB = smem_u32(&Bs[0][0][0]);

    int row0 = blockIdx.y * 64, col0 = blockIdx.x * 64;
    const __nv_bfloat16* A = sel ? g_Wvfb : (g_Wqkvb + 2*DD);
    int lda = sel ? DD : W3;
    const __nv_bfloat16* B = sel ? g_Wfc2 : g_Wfc1b;
    int tid = threadIdx.x, w = tid >> 5, lane = tid & 31;
    int wm = w >> 2, wn = w & 3;

    wmma::fragment<wmma::accumulator,16,16,16,float> acc[2];
    #pragma unroll
    for (int i = 0; i < 2; i++) wmma::fill_fragment(acc[i], 0.f);

    #define W64_STAGE(kc, bb) {                                                    \
        _Pragma("unroll")                                                          \
        for (int r = 0; r < 2; r++) {                                              \
            int idx = tid + r*256;                                                 \
            int ar = idx >> 3, ac = (idx & 7) * 8;                                 \
            CPA16(sA + (uint32_t)(bb)*9216u + (uint32_t)ar*144u + (uint32_t)ac*2u, \
                  A + (size_t)(row0+ar)*lda + (kc) + ac);                          \
        }                                                                          \
        _Pragma("unroll")                                                          \
        for (int r = 0; r < 2; r++) {                                              \
            int idx = tid + r*256;                                                 \
            int br = idx >> 3, bc = (idx & 7) * 8;                                 \
            CPA16(sB + (uint32_t)(bb)*9216u + (uint32_t)br*144u + (uint32_t)bc*2u, \
                  B + (size_t)((kc)+br)*DD + col0 + bc);                           \
        }                                                                          \
        CPA_COMMIT(); }

    W64_STAGE(0, 0);
    for (int s = 0; s < 4; s++) {
        CPA_WAIT(0);
        __syncthreads();
        if (s < 3) W64_STAGE((s+1)*64, (s+1)&1);
        int bb = s & 1;
        #pragma unroll
        for (int k4 = 0; k4 < 4; k4++) {
            wmma::fragment<wmma::matrix_a,16,16,16,__nv_bfloat16,wmma::row_major> af[2];
            wmma::fragment<wmma::matrix_b,16,16,16,__nv_bfloat16,wmma::row_major> bf;
            #pragma unroll
            for (int i = 0; i < 2; i++)
                wmma::load_matrix_sync(af[i], &As[bb][wm*32 + i*16][k4*16], 72);
            wmma::load_matrix_sync(bf, &Bs[bb][k4*16][wn*16], 72);
            #pragma unroll
            for (int i = 0; i < 2; i++)
                wmma::mma_sync(acc[i], af[i], bf, acc[i]);
        }
    }
    #undef W64_STAGE
    __syncthreads();

    int r = lane >> 1, c8 = (lane & 1) * 8;
    #pragma unroll
    for (int i = 0; i < 2; i++) {
        wmma::store_matrix_sync(&epi[w][0][0], acc[i], 16, wmma::mem_row_major);
        __syncwarp();
        int gr = row0 + wm*32 + i*16 + r;
        int gc = col0 + wn*16 + c8;
        if (sel) {
            *(float4*)(g_Wvf2 + (size_t)gr*DD + gc)     = *(float4*)(&epi[w][r][c8]);
            *(float4*)(g_Wvf2 + (size_t)gr*DD + gc + 4) = *(float4*)(&epi[w][r][c8+4]);
        } else {
            __nv_bfloat16 t8[8];
            #pragma unroll
            for (int e = 0; e < 8; e++)
                t8[e] = __float2bfloat16(epi[w][r][c8+e]);
            *(uint4*)(g_Wvfb + (size_t)gr*DD + gc) = *(uint4*)t8;
        }
        __syncwarp();
    }
}

// ---------------- dbias, bvf, bvf2 ------------------------------------------
__global__ void dbias_k(const float* __restrict__ bqkv) {
    __shared__ float red[256];
    int a = blockIdx.x, i = threadIdx.x;
    red[i] = bqkv[i] * g_kaf[a*DD + i];
    __syncthreads();
    for (int st = 128; st > 0; st >>= 1) {
        if (i < st) red[i] += red[i + st];
        __syncthreads();
    }
    if (i == 0) g_dbias[a] = red[0];
}
__global__ void bvf_k(const float* __restrict__ Wfc1,
                      const float* __restrict__ bqkv, const float* __restrict__ bfc1) {
    int j = threadIdx.x;
    float t = bfc1[j];
    #pragma unroll 8
    for (int o = 0; o < DD; o++)
        t += bqkv[2*DD + o] * Wfc1[o*DD + j];
    g_bvf[j] = t;
}
__global__ void bvf2_k(const float* __restrict__ Wfc2) {
    int j = threadIdx.x;
    float t = 0.f;
    #pragma unroll 8
    for (int o = 0; o < DD; o++)
        t += g_bvf[o] * Wfc2[o*DD + j];
    g_bvf2[j] = t;
}

// ======== fused stage-1: logits -> split softmax -> unnormalized P@x ========
// grid (SPL, NB), 256 threads. smem layout:
//  L  [64][272] bf16  @0      : 34816  (logits -> probs, in place)
//  pass1 Qa[2][64][40]@34816  : 10240 ; Ks[2][128][40]@45056 : 20480
//  pass2 Vs[2][32][264]@34816 : 33792
//  epi [8][16][16] f32 @68608 : 8192        total 76800
__global__ void __launch_bounds__(256) s1fused() {
    extern __shared__ __align__(16) char smf[];
    __nv_bfloat16 (*L)[272]      = ( __nv_bfloat16(*)[272]) smf;
    __nv_bfloat16 (*Qa)[64][40]  = ( __nv_bfloat16(*)[64][40]) (smf + 34816);
    __nv_bfloat16 (*Ks)[128][40] = ( __nv_bfloat16(*)[128][40])(smf + 45056);
    __nv_bfloat16 (*Vs)[32][264] = ( __nv_bfloat16(*)[32][264])(smf + 34816);
    float (*epi)[16][16]         = ( float(*)[16][16])         (smf + 68608);
    uint32_t sQ = smem_u32(smf) + 34816u;
    uint32_t sK = smem_u32(smf) + 45056u;
    uint32_t sV = smem_u32(smf) + 34816u;

    int split = blockIdx.x, b = blockIdx.y;
    int tok0 = split * TSPL;
    int tid = threadIdx.x;
    int w = tid >> 5, lane = tid & 31;
    int wm = w >> 2, wn = w & 3;

    // ---- pass 1: logits[64, 256] in two 128-token tiles ----
    #define F1_STAGE(kc, bb, col0) {                                               \
        {   int ar = tid >> 2, ac = (tid & 3) * 8;                                 \
            CPA16(sQ + (uint32_t)(bb)*5120u + (uint32_t)ar*80u + (uint32_t)ac*2u,  \
                  g_qap + (size_t)ar*DD + (kc) + ac); }                            \
        _Pragma("unroll")                                                          \
        for (int r = 0; r < 2; r++) {                                              \
            int idx = tid + r*256;                                                 \
            int kr = idx >> 2, kcc = (idx & 3) * 8;                                \
            CPA16(sK + (uint32_t)(bb)*10240u + (uint32_t)kr*80u + (uint32_t)kcc*2u,\
                  g_xb + (size_t)(b*NT + (col0) + kr)*DD + (kc) + kcc);            \
        }                                                                          \
        CPA_COMMIT(); }

    #pragma unroll 1
    for (int t = 0; t < 2; t++) {
        int col0 = tok0 + t*128;
        wmma::fragment<wmma::accumulator,16,16,16,float> acc[2][2];
        #pragma unroll
        for (int i = 0; i < 2; i++)
            #pragma unroll
            for (int j = 0; j < 2; j++) wmma::fill_fragment(acc[i][j], 0.f);

        F1_STAGE(0, 0, col0);
        for (int s = 0; s < 8; s++) {
            CPA_WAIT(0);
            __syncthreads();
            if (s < 7) F1_STAGE((s+1)*32, (s+1)&1, col0);
            int bb = s & 1;
            #pragma unroll
            for (int kk = 0; kk < 2; kk++) {
                wmma::fragment<wmma::matrix_a,16,16,16,__nv_bfloat16,wmma::row_major> af[2];
                wmma::fragment<wmma::matrix_b,16,16,16,__nv_bfloat16,wmma::col_major> bf[2];
                #pragma unroll
                for (int i = 0; i < 2; i++)
                    wmma::load_matrix_sync(af[i], &Qa[bb][wm*32 + i*16][kk*16], 40);
                #pragma unroll
                for (int j = 0; j < 2; j++)
                    wmma::load_matrix_sync(bf[j], &Ks[bb][wn*32 + j*16][kk*16], 40);
                #pragma unroll
                for (int i = 0; i < 2; i++)
                    #pragma unroll
                    for (int j = 0; j < 2; j++)
                        wmma::mma_sync(acc[i][j], af[i], bf[j], acc[i][j]);
            }
        }
        // epilogue: logits tile -> L (bf16)
        __syncthreads();
        #pragma unroll
        for (int i = 0; i < 2; i++)
            #pragma unroll
            for (int j = 0; j < 2; j++) {
                wmma::store_matrix_sync(&epi[w][0][0], acc[i][j], 16, wmma::mem_row_major);
                __syncwarp();
                if (lane < 16) {
                    int ga = wm*32 + i*16 + lane;
                    int gc = t*128 + wn*32 + j*16;
                    __nv_bfloat16 t8[8];
                    #pragma unroll
                    for (int g = 0; g < 2; g++) {
                        #pragma unroll
                        for (int e = 0; e < 8; e++)
                            t8[e] = __float2bfloat16(epi[w][lane][g*8+e]);
                        *(uint4*)(&L[ga][gc + g*8]) = *(uint4*)t8;
                    }
                }
                __syncwarp();
            }
        __syncthreads();
    }
    #undef F1_STAGE

    // ---- split softmax over 256 cols: row = tid>>2, 4 threads/row ----
    {
        int row = tid >> 2, q = tid & 3;
        float m = -1e30f;
        #pragma unroll 8
        for (int c = 0; c < 64; c++)
            m = fmaxf(m, __bfloat162float(L[row][q*64 + c]));
        m = fmaxf(m, __shfl_xor_sync(0xffffffffu, m, 1));
        m = fmaxf(m, __shfl_xor_sync(0xffffffffu, m, 2));
        float sum = 0.f;
        #pragma unroll 8
        for (int c = 0; c < 64; c++) {
            float p = __expf(__bfloat162float(L[row][q*64 + c]) - m);
            sum += p;
            L[row][q*64 + c] = __float2bfloat16(p);
        }
        sum += __shfl_xor_sync(0xffffffffu, sum, 1);
        sum += __shfl_xor_sync(0xffffffffu, sum, 2);
        if (q == 0)
            g_stats[(b*SPL + split)*NA + row] = make_float2(m, sum);
    }
    __syncthreads();

    // ---- pass 2: u_split[64,256] = P[64,256] @ x_split[256,256] ----
    {
        wmma::fragment<wmma::accumulator,16,16,16,float> acc[2][4];
        #pragma unroll
        for (int i = 0; i < 2; i++)
            #pragma unroll
            for (int j = 0; j < 4; j++) wmma::fill_fragment(acc[i][j], 0.f);

        #define F2_STAGE(kc, bb) {                                                 \
            _Pragma("unroll")                                                      \
            for (int r = 0; r < 4; r++) {                                          \
                int idx = tid + r*256;                                             \
                int vr = idx >> 5, vc = (idx & 31) * 8;                            \
                CPA16(sV + (uint32_t)(bb)*16896u + (uint32_t)vr*528u + (uint32_t)vc*2u,\
                      g_xb + (size_t)(b*NT + tok0 + (kc) + vr)*DD + vc);           \
            }                                                                      \
            CPA_COMMIT(); }

        F2_STAGE(0, 0);
        for (int s = 0; s < 8; s++) {
            CPA_WAIT(0);
            __syncthreads();
            if (s < 7) F2_STAGE((s+1)*32, (s+1)&1);
            int bb = s & 1;
            #pragma unroll
            for (int kk = 0; kk < 2; kk++) {
                wmma::fragment<wmma::matrix_a,16,16,16,__nv_bfloat16,wmma::row_major> af[2];
                wmma::fragment<wmma::matrix_b,16,16,16,__nv_bfloat16,wmma::row_major> bf[4];
                #pragma unroll
                for (int i = 0; i < 2; i++)
                    wmma::load_matrix_sync(af[i], &L[wm*32 + i*16][s*32 + kk*16], 272);
                #pragma unroll
                for (int j = 0; j < 4; j++)
                    wmma::load_matrix_sync(bf[j], &Vs[bb][kk*16][wn*64 + j*16], 264);
                #pragma unroll
                for (int i = 0; i < 2; i++)
                    #pragma unroll
                    for (int j = 0; j < 4; j++)
                        wmma::mma_sync(acc[i][j], af[i], bf[j], acc[i][j]);
            }
        }
        #undef F2_STAGE
        __syncthreads();

        float* outb = g_vap + (size_t)(b*SPL + split)*NA*DD;
        #pragma unroll
        for (int i = 0; i < 2; i++)
            #pragma unroll
            for (int j = 0; j < 4; j++) {
                wmma::store_matrix_sync(&epi[w][0][0], acc[i][j], 16, wmma::mem_row_major);
                __syncwarp();
                #pragma unroll
                for (int e = 0; e < 2; e++) {
                    int idx2 = lane + e*32;
                    int r = idx2 >> 2, c4 = (idx2 & 3) * 4;
                    int ga = wm*32 + i*16 + r;
                    int gd = wn*64 + j*16 + c4;
                    *(float4*)(outb + (size_t)ga*DD + gd) = *(float4*)(&epi[w][r][c4]);
                }
                __syncwarp();
            }
    }
}

// ---------------- fc1: combine splits (rescale), then va2 = u @ Wvf2 + bvf2 --
__global__ void fc1k() {
    __shared__ float r0[DD];
    __shared__ float ms[SPL], ss[SPL];
    int row = blockIdx.x;  // b*NA + a
    int b = row >> 6, a = row & 63;
    int i = threadIdx.x;

    if (i < SPL) {
        float2 st = g_stats[(b*SPL + i)*NA + a];
        ms[i] = st.x; ss[i] = st.y;
    }
    __syncthreads();
    float m = -1e30f;
    #pragma unroll
    for (int s = 0; s < SPL; s++) m = fmaxf(m, ms[s]);
    float S = 0.f;
    float wsc[SPL];
    #pragma unroll
    for (int s = 0; s < SPL; s++) {
        wsc[s] = __expf(ms[s] - m);
        S += wsc[s] * ss[s];
    }
    float acc = 0.f;
    #pragma unroll
    for (int s = 0; s < SPL; s++)
        acc += wsc[s] * g_vap[(size_t)(b*SPL + s)*NA*DD + (size_t)a*DD + i];
    r0[i] = acc / S;
    __syncthreads();
    int o = threadIdx.x;
    float sum = g_bvf2[o];
    #pragma unroll 8
    for (int d = 0; d < DD; d++) sum += r0[d] * g_Wvf2[d*DD + o];
    g_va[(size_t)row*DD + o] = __float2bfloat16(sum);
}

// ---------------- stage 2 fused: logits -> softmax -> P@va2 + bfc2 + x -------
__global__ void __launch_bounds__(256) stage2(const float* __restrict__ bfc2,
                                              const float* __restrict__ x,
                                              float* __restrict__ out) {
    extern __shared__ __align__(16) char sm2[];
    __nv_bfloat16 (*Qs)[128][40] = ( __nv_bfloat16(*)[128][40]) sm2;             // 20480
    __nv_bfloat16 (*Ka)[64][40]  = ( __nv_bfloat16(*)[64][40]) (sm2 + 20480);    // 10240
    float* logits                = ( float*)                   (sm2 + 30720);    // 34816
    __nv_bfloat16 (*Vs)[264]     = ( __nv_bfloat16(*)[264])    (sm2 + 65536);    // 33792
    __nv_bfloat16 (*Pm)[72]      = ( __nv_bfloat16(*)[72])     sm2;              // reuse Qs
    float (*epi)[16][16]         = ( float(*)[16][16])         (sm2 + 20480);    // reuse Ka
    __shared__ float dbs[NA];
    uint32_t sQ = smem_u32(sm2), sKa = sQ + 20480u, sV = sQ + 65536u;

    int b = blockIdx.y, t0 = blockIdx.x * 128;
    int tid = threadIdx.x;
    int w = tid >> 5, lane = tid & 31;

    if (tid < NA) dbs[tid] = g_dbias[tid];

    #pragma unroll
    for (int r = 0; r < 8; r++) {
        int idx = tid + r*256;
        int vr = idx >> 5, vc = (idx & 31) * 8;
        CPA16(sV + (uint32_t)vr*528u + (uint32_t)vc*2u,
              g_va + (size_t)(b*NA + vr)*DD + vc);
    }
    CPA_COMMIT();

    // --- phase A: logits[128,64] = x_tile @ Ka'^T ---
    {
        int wm = w >> 1, wn = w & 1;
        wmma::fragment<wmma::accumulator,16,16,16,float> acc[2][2];
        #pragma unroll
        for (int i = 0; i < 2; i++)
            #pragma unroll
            for (int j = 0; j < 2; j++) wmma::fill_fragment(acc[i][j], 0.f);

        #define S2_STAGE(kc, bb) {                                                 \
            _Pragma("unroll")                                                      \
            for (int r = 0; r < 2; r++) {                                          \
                int idx = tid + r*256;                                             \
                int qr = idx >> 2, qc = (idx & 3) * 8;                             \
                CPA16(sQ + (uint32_t)(bb)*10240u + (uint32_t)qr*80u + (uint32_t)qc*2u, \
                      g_xb + (size_t)(b*NT + t0 + qr)*DD + (kc) + qc);             \
            }                                                                      \
            {   int ar = tid >> 2, ac = (tid & 3) * 8;                             \
                CPA16(sKa + (uint32_t)(bb)*5120u + (uint32_t)ar*80u + (uint32_t)ac*2u, \
                      g_kat + (size_t)ar*DD + (kc) + ac); }                        \
            CPA_COMMIT(); }

        S2_STAGE(0, 0);
        for (int s = 0; s < 8; s++) {
            CPA_WAIT(0);
            __syncthreads();
            if (s < 7) S2_STAGE((s+1)*32, (s+1)&1);
            int bb = s & 1;
            #pragma unroll
            for (int kk = 0; kk < 2; kk++) {
                wmma::fragment<wmma::matrix_a,16,16,16,__nv_bfloat16,wmma::row_major> af[2];
                wmma::fragment<wmma::matrix_b,16,16,16,__nv_bfloat16,wmma::col_major> bf[2];
                #pragma unroll
                for (int i = 0; i < 2; i++)
                    wmma::load_matrix_sync(af[i], &Qs[bb][wm*32 + i*16][kk*16], 40);
                #pragma unroll
                for (int j = 0; j < 2; j++)
                    wmma::load_matrix_sync(bf[j], &Ka[bb][wn*32 + j*16][kk*16], 40);
                #pragma unroll
                for (int i = 0; i < 2; i++)
                    #pragma unroll
                    for (int j = 0; j < 2; j++)
                        wmma::mma_sync(acc[i][j], af[i], bf[j], acc[i][j]);
            }
        }
        #undef S2_STAGE
        __syncthreads();
        #pragma unroll
        for (int i = 0; i < 2; i++)
            #pragma unroll
            for (int j = 0; j < 2; j++)
                wmma::store_matrix_sync(logits + (wm*32 + i*16)*68 + wn*32 + j*16,
                                        acc[i][j], 68, wmma::mem_row_major);
    }
    __syncthreads();

    // --- phase B: per-row softmax over 64 agents (+dbias) -> Pm ---
    if (tid < 128) {
        const float* lr = logits + tid*68;
        float lv[64];
        #pragma unroll 8
        for (int c = 0; c < 64; c++) lv[c] = lr[c] + dbs[c];
        float m = -1e30f;
        #pragma unroll 8
        for (int c = 0; c < 64; c++) m = fmaxf(m, lv[c]);
        float sum = 0.f;
        #pragma unroll 8
        for (int c = 0; c < 64; c++) sum += __expf(lv[c] - m);
        float inv = 1.f / sum;
        #pragma unroll 8
        for (int c = 0; c < 64; c++)
            Pm[tid][c] = __float2bfloat16(__expf(lv[c] - m) * inv);
    }
    __syncthreads();

    // --- phase C: out[128,256] = Pm @ Vs + bfc2 + x ---
    {
        int wm = w >> 1, wn = w & 1;
        for (int nc = 0; nc < 2; nc++) {
            wmma::fragment<wmma::accumulator,16,16,16,float> acc[2][4];
            #pragma unroll
            for (int i = 0; i < 2; i++)
                #pragma unroll
                for (int j = 0; j < 4; j++) wmma::fill_fragment(acc[i][j], 0.f);
            #pragma unroll
            for (int kk = 0; kk < 4; kk++) {
                wmma::fragment<wmma::matrix_a,16,16,16,__nv_bfloat16,wmma::row_major> af[2];
                wmma::fragment<wmma::matrix_b,16,16,16,__nv_bfloat16,wmma::row_major> bf[4];
                #pragma unroll
                for (int i = 0; i < 2; i++)
                    wmma::load_matrix_sync(af[i], &Pm[wm*32 + i*16][kk*16], 72);
                #pragma unroll
                for (int j = 0; j < 4; j++)
                    wmma::load_matrix_sync(bf[j], &Vs[kk*16][nc*128 + wn*64 + j*16], 264);
                #pragma unroll
                for (int i = 0; i < 2; i++)
                    #pragma unroll
                    for (int j = 0; j < 4; j++)
                        wmma::mma_sync(acc[i][j], af[i], bf[j], acc[i][j]);
            }
            int r = lane >> 1, c8 = (lane & 1) * 8;
            #pragma unroll
            for (int i = 0; i < 2; i++)
                #pragma unroll
                for (int j = 0; j < 4; j++) {
                    wmma::store_matrix_sync(&epi[w][0][0], acc[i][j], 16, wmma::mem_row_major);
                    __syncwarp();
                    int grow = t0 + wm*32 + i*16 + r;
                    int gcol = nc*128 + wn*64 + j*16 + c8;
                    size_t gi = (size_t)(b*NT + grow)*DD + gcol;
                    float o0[4], o1[4];
                    #pragma unroll
                    for (int e = 0; e < 4; e++)
                        o0[e] = epi[w][r][c8+e]   + bfc2[gcol+e]   + x[gi+e];
                    #pragma unroll
                    for (int e = 0; e < 4; e++)
                        o1[e] = epi[w][r][c8+4+e] + bfc2[gcol+4+e] + x[gi+4+e];
                    *(float4*)(out + gi)     = *(float4*)o0;
                    *(float4*)(out + gi + 4) = *(float4*)o1;
                    __syncwarp();
                }
        }
    }
}

// ---------------- launcher ---------------------------------------------------
#define S1F_SMEM 76800

extern "C" void kernel_launch(void* const* d_in, const int* in_sizes, int n_in,
                              void* d_out, int out_size) {
    const float* agent = (const float*)d_in[0];
    const float* x     = (const float*)d_in[1];
    const float* Wqkv  = (const float*)d_in[2];
    const float* bqkv  = (const float*)d_in[3];
    const float* Wag   = (const float*)d_in[4];
    const float* bag   = (const float*)d_in[5];
    const float* Wfc1  = (const float*)d_in[6];
    const float* bfc1  = (const float*)d_in[7];
    const float* Wfc2  = (const float*)d_in[8];
    const float* bfc2  = (const float*)d_in[9];
    float* out = (float*)d_out;

    cudaFuncSetAttribute(stage2,  cudaFuncAttributeMaxDynamicSharedMemorySize, 99328);
    cudaFuncSetAttribute(s1fused, cudaFuncAttributeMaxDynamicSharedMemorySize, S1F_SMEM);

    conv_inputs<<<2048, 256>>>(x, Wfc2, Wqkv, Wfc1);
    agent_proj<<<64, 512>>>(agent, Wag, bag);
    proj_agents<<<dim3(4, 2), 256>>>();
    w64_gemm<<<dim3(4, 4), 256>>>(0);   // Wvfb = Wv @ Wfc1 (bf16)
    w64_gemm<<<dim3(4, 4), 256>>>(1);   // Wvf2 = Wvfb @ Wfc2 (f32)
    dbias_k<<<64, 256>>>(bqkv);
    bvf_k<<<1, 256>>>(Wfc1, bqkv, bfc1);
    bvf2_k<<<1, 256>>>(Wfc2);
    s1fused<<<dim3(SPL, NB), 256, S1F_SMEM>>>();
    fc1k<<<512, 256>>>();
    stage2<<<dim3(32, 8), 256, 99328>>>(bfc2, x, out);
}

// round 11
// speedup vs baseline: 1.8870x; 1.1939x over previous
#include <cuda_runtime.h>
#include <cuda_bf16.h>
#include <mma.h>
#include <cstdint>

using namespace nvcuda;

#define NB 8
#define NT 4096
#define NA 64
#define DD 256
#define MTOK (NB*NT)
#define W3 (3*DD)
#define SPL 16
#define TSPL 256   // tokens per split

// ---------------- scratch (device globals; no allocations allowed) ----------
__device__ __nv_bfloat16 g_xb[MTOK*DD];              // x in bf16
__device__ __nv_bfloat16 g_Wfc2[DD*DD];              // W_fc2 bf16 [K,N]
__device__ __nv_bfloat16 g_Wqkvb[DD*W3];             // W_qkv bf16 [K, 3N]
__device__ __nv_bfloat16 g_Wfc1b[DD*DD];             // W_fc1 bf16 [K,N]
__device__ __nv_bfloat16 g_qasb[NA*DD];              // qa_s bf16 (scale folded)
__device__ __nv_bfloat16 g_kasb[NA*DD];              // ka_s bf16 (scale folded)
__device__ float        g_kaf[NA*DD];                // ka_s fp32 (for dbias)
__device__ __nv_bfloat16 g_qap[NA*DD];               // qa' = qa_s @ Wk^T, bf16
__device__ __nv_bfloat16 g_kat[NA*DD];               // Ka' [a,i] bf16
__device__ float        g_dbias[NA];                 // bq . ka_s
__device__ __nv_bfloat16 g_Wvfb[DD*DD];              // Wv @ Wfc1, bf16
__device__ float        g_Wvf2[DD*DD];               // (Wv@Wfc1)@Wfc2, fp32
__device__ float        g_bvf[DD];                   // bv@Wfc1 + bfc1
__device__ float        g_bvf2[DD];                  // bvf @ Wfc2
__device__ float        g_vap[NB*SPL*NA*DD];         // unnormalized split partials
__device__ float2       g_stats[NB*SPL*NA];          // (m_s, s_s) per split-row
__device__ __nv_bfloat16 g_va[NB*NA*DD];             // va2 bf16

// ---------------- cp.async helpers ------------------------------------------
__device__ __forceinline__ uint32_t smem_u32(const void* p) {
    uint32_t a;
    asm("{ .reg .u64 t; cvta.to.shared.u64 t, %1; cvt.u32.u64 %0, t; }" : "=r"(a) : "l"(p));
    return a;
}
#define CPA16(s, g)  asm volatile("cp.async.cg.shared.global [%0], [%1], 16;" :: "r"(s), "l"(g))
#define CPA_COMMIT() asm volatile("cp.async.commit_group;" ::: "memory")
#define CPA_WAIT(n)  asm volatile("cp.async.wait_group %0;" :: "n"(n) : "memory")

// ================= prep0: conv_inputs || agent_proj ==========================
// grid 1088 x 512 threads. blocks [0,1024): conversions; [1024,1088): agents
__global__ void __launch_bounds__(512) prep0(const float* __restrict__ x,
                                             const float* __restrict__ Wfc2,
                                             const float* __restrict__ Wqkv,
                                             const float* __restrict__ Wfc1,
                                             const float* __restrict__ agent,
                                             const float* __restrict__ Wag,
                                             const float* __restrict__ bag) {
    if (blockIdx.x < 1024) {
        int tid = blockIdx.x * 512 + threadIdx.x;
        int stride = 1024 * 512;
        for (int i = tid; i < (MTOK*DD)/4; i += stride) {
            float4 v = *(const float4*)(x + i*4);
            __nv_bfloat16 t[4] = {__float2bfloat16(v.x), __float2bfloat16(v.y),
                                  __float2bfloat16(v.z), __float2bfloat16(v.w)};
            *(uint2*)(g_xb + i*4) = *(uint2*)t;
        }
        for (int i = tid; i < DD*DD; i += stride)
            g_Wfc2[i] = __float2bfloat16(Wfc2[i]);
        for (int i = tid; i < DD*W3; i += stride)
            g_Wqkvb[i] = __float2bfloat16(Wqkv[i]);
        for (int i = tid; i < DD*DD; i += stride)
            g_Wfc1b[i] = __float2bfloat16(Wfc1[i]);
    } else {
        __shared__ float arow[DD];
        int a = blockIdx.x - 1024;
        for (int i = threadIdx.x; i < DD; i += 512)
            arow[i] = agent[a*DD + i];
        __syncthreads();
        int o = threadIdx.x;  // 0..511
        float s = 0.f;
        #pragma unroll 8
        for (int d = 0; d < DD; d++)
            s += arow[d] * Wag[d*2*DD + o];
        s += bag[o];
        s *= 0.0625f;  // 256^-0.5
        if (o < DD) {
            g_qasb[a*DD + o] = __float2bfloat16(s);
        } else {
            g_kasb[a*DD + (o-DD)] = __float2bfloat16(s);
            g_kaf [a*DD + (o-DD)] = s;
        }
    }
}

// ---------------- device: proj_agents tile -----------------------------------
__device__ void dev_proj_agents(char* sm, int ix, int sel) {
    __nv_bfloat16 (*Aa)[64][40] = (__nv_bfloat16(*)[64][40]) sm;
    __nv_bfloat16 (*Ws)[64][40] = (__nv_bfloat16(*)[64][40])(sm + 10240);
    float (*epi)[16][16]        = (float(*)[16][16])        (sm + 20480);
    uint32_t sA = smem_u32(sm), sW = sA + 10240u;

    int col0 = ix * 64;
    const __nv_bfloat16* A  = sel ? g_kasb : g_qasb;
    const __nv_bfloat16* Bb = g_Wqkvb + (sel ? 0 : DD);
    __nv_bfloat16* C = sel ? g_kat : g_qap;
    int tid = threadIdx.x;
    int w = tid >> 5, lane = tid & 31;
    int wm = w >> 2, wn = w & 3;

    wmma::fragment<wmma::accumulator,16,16,16,float> acc[2];
    #pragma unroll
    for (int i = 0; i < 2; i++) wmma::fill_fragment(acc[i], 0.f);

    #define PA_STAGE(kc, bb) {                                                     \
        {   int ar = tid >> 2, ac = (tid & 3) * 8;                                 \
            CPA16(sA + (uint32_t)(bb)*5120u + (uint32_t)ar*80u + (uint32_t)ac*2u,  \
                  A + (size_t)ar*DD + (kc) + ac); }                                \
        {   int wr = tid >> 2, wc = (tid & 3) * 8;                                 \
            CPA16(sW + (uint32_t)(bb)*5120u + (uint32_t)wr*80u + (uint32_t)wc*2u,  \
                  Bb + (size_t)(col0 + wr)*W3 + (kc) + wc); }                      \
        CPA_COMMIT(); }

    PA_STAGE(0, 0);
    for (int s = 0; s < 8; s++) {
        CPA_WAIT(0);
        __syncthreads();
        if (s < 7) PA_STAGE((s+1)*32, (s+1)&1);
        int bb = s & 1;
        #pragma unroll
        for (int kk = 0; kk < 2; kk++) {
            wmma::fragment<wmma::matrix_a,16,16,16,__nv_bfloat16,wmma::row_major> af[2];
            wmma::fragment<wmma::matrix_b,16,16,16,__nv_bfloat16,wmma::col_major> bf;
            #pragma unroll
            for (int i = 0; i < 2; i++)
                wmma::load_matrix_sync(af[i], &Aa[bb][wm*32 + i*16][kk*16], 40);
            wmma::load_matrix_sync(bf, &Ws[bb][wn*16][kk*16], 40);
            #pragma unroll
            for (int i = 0; i < 2; i++)
                wmma::mma_sync(acc[i], af[i], bf, acc[i]);
        }
    }
    #undef PA_STAGE

    #pragma unroll
    for (int i = 0; i < 2; i++) {
        wmma::store_matrix_sync(&epi[w][0][0], acc[i], 16, wmma::mem_row_major);
        __syncwarp();
        if (lane < 16) {
            int a = wm*32 + i*16 + lane;
            __nv_bfloat16 t8[8];
            #pragma unroll
            for (int g = 0; g < 2; g++) {
                #pragma unroll
                for (int e = 0; e < 8; e++)
                    t8[e] = __float2bfloat16(epi[w][lane][g*8+e]);
                *(uint4*)(C + (size_t)a*DD + col0 + wn*16 + g*8) = *(uint4*)t8;
            }
        }
        __syncwarp();
    }
}

// ---------------- device: 64x64 weight GEMM tile -----------------------------
__device__ void dev_w64(char* sm, int bx, int by, int sel) {
    __nv_bfloat16 (*As)[64][72] = (__nv_bfloat16(*)[64][72]) sm;
    __nv_bfloat16 (*Bs)[64][72] = (__nv_bfloat16(*)[64][72])(sm + 18432);
    float (*epi)[16][16]        = (float(*)[16][16])        (sm + 36864);
    uint32_t sA = smem_u32(sm), sB = sA + 18432u;

    int row0 = by * 64, col0 = bx * 64;
    const __nv_bfloat16* A = sel ? g_Wvfb : (g_Wqkvb + 2*DD);
    int lda = sel ? DD : W3;
    const __nv_bfloat16* B = sel ? g_Wfc2 : g_Wfc1b;
    int tid = threadIdx.x, w = tid >> 5, lane = tid & 31;
    int wm = w >> 2, wn = w & 3;

    wmma::fragment<wmma::accumulator,16,16,16,float> acc[2];
    #pragma unroll
    for (int i = 0; i < 2; i++) wmma::fill_fragment(acc[i], 0.f);

    #define W64_STAGE(kc, bb) {                                                    \
        _Pragma("unroll")                                                          \
        for (int r = 0; r < 2; r++) {                                              \
            int idx = tid + r*256;                                                 \
            int ar = idx >> 3, ac = (idx & 7) * 8;                                 \
            CPA16(sA + (uint32_t)(bb)*9216u + (uint32_t)ar*144u + (uint32_t)ac*2u, \
                  A + (size_t)(row0+ar)*lda + (kc) + ac);                          \
        }                                                                          \
        _Pragma("unroll")                                                          \
        for (int r = 0; r < 2; r++) {                                              \
            int idx = tid + r*256;                                                 \
            int br = idx >> 3, bc = (idx & 7) * 8;                                 \
            CPA16(sB + (uint32_t)(bb)*9216u + (uint32_t)br*144u + (uint32_t)bc*2u, \
                  B + (size_t)((kc)+br)*DD + col0 + bc);                           \
        }                                                                          \
        CPA_COMMIT(); }

    W64_STAGE(0, 0);
    for (int s = 0; s < 4; s++) {
        CPA_WAIT(0);
        __syncthreads();
        if (s < 3) W64_STAGE((s+1)*64, (s+1)&1);
        int bb = s & 1;
        #pragma unroll
        for (int k4 = 0; k4 < 4; k4++) {
            wmma::fragment<wmma::matrix_a,16,16,16,__nv_bfloat16,wmma::row_major> af[2];
            wmma::fragment<wmma::matrix_b,16,16,16,__nv_bfloat16,wmma::row_major> bf;
            #pragma unroll
            for (int i = 0; i < 2; i++)
                wmma::load_matrix_sync(af[i], &As[bb][wm*32 + i*16][k4*16], 72);
            wmma::load_matrix_sync(bf, &Bs[bb][k4*16][wn*16], 72);
            #pragma unroll
            for (int i = 0; i < 2; i++)
                wmma::mma_sync(acc[i], af[i], bf, acc[i]);
        }
    }
    #undef W64_STAGE
    __syncthreads();

    int r = lane >> 1, c8 = (lane & 1) * 8;
    #pragma unroll
    for (int i = 0; i < 2; i++) {
        wmma::store_matrix_sync(&epi[w][0][0], acc[i], 16, wmma::mem_row_major);
        __syncwarp();
        int gr = row0 + wm*32 + i*16 + r;
        int gc = col0 + wn*16 + c8;
        if (sel) {
            *(float4*)(g_Wvf2 + (size_t)gr*DD + gc)     = *(float4*)(&epi[w][r][c8]);
            *(float4*)(g_Wvf2 + (size_t)gr*DD + gc + 4) = *(float4*)(&epi[w][r][c8+4]);
        } else {
            __nv_bfloat16 t8[8];
            #pragma unroll
            for (int e = 0; e < 8; e++)
                t8[e] = __float2bfloat16(epi[w][r][c8+e]);
            *(uint4*)(g_Wvfb + (size_t)gr*DD + gc) = *(uint4*)t8;
        }
        __syncwarp();
    }
}

// ================= prep1: proj_agents || w64(0) || dbias || bvf ==============
// grid 89 x 256 threads, dyn smem 45056
__global__ void __launch_bounds__(256) prep1(const float* __restrict__ bqkv,
                                             const float* __restrict__ Wfc1,
                                             const float* __restrict__ bfc1) {
    extern __shared__ __align__(16) char sm[];
    int bid = blockIdx.x;
    if (bid < 8) {
        dev_proj_agents(sm, bid & 3, bid >> 2);
    } else if (bid < 24) {
        int t = bid - 8;
        dev_w64(sm, t & 3, t >> 2, 0);
    } else if (bid < 88) {
        float* red = (float*)sm;
        int a = bid - 24, i = threadIdx.x;
        red[i] = bqkv[i] * g_kaf[a*DD + i];
        __syncthreads();
        for (int st = 128; st > 0; st >>= 1) {
            if (i < st) red[i] += red[i + st];
            __syncthreads();
        }
        if (i == 0) g_dbias[a] = red[0];
    } else {
        int j = threadIdx.x;
        float t = bfc1[j];
        #pragma unroll 8
        for (int o = 0; o < DD; o++)
            t += bqkv[2*DD + o] * Wfc1[o*DD + j];
        g_bvf[j] = t;
    }
}

// ================= prep2: w64(1) || bvf2 =====================================
__global__ void __launch_bounds__(256) prep2(const float* __restrict__ Wfc2) {
    extern __shared__ __align__(16) char sm[];
    int bid = blockIdx.x;
    if (bid < 16) {
        dev_w64(sm, bid & 3, bid >> 2, 1);
    } else {
        int j = threadIdx.x;
        float t = 0.f;
        #pragma unroll 8
        for (int o = 0; o < DD; o++)
            t += g_bvf[o] * Wfc2[o*DD + j];
        g_bvf2[j] = t;
    }
}

// ======== fused stage-1: logits -> split softmax -> unnormalized P@x ========
__global__ void __launch_bounds__(256) s1fused() {
    extern __shared__ __align__(16) char smf[];
    __nv_bfloat16 (*L)[272]      = ( __nv_bfloat16(*)[272]) smf;
    __nv_bfloat16 (*Qa)[64][40]  = ( __nv_bfloat16(*)[64][40]) (smf + 34816);
    __nv_bfloat16 (*Ks)[128][40] = ( __nv_bfloat16(*)[128][40])(smf + 45056);
    __nv_bfloat16 (*Vs)[32][264] = ( __nv_bfloat16(*)[32][264])(smf + 34816);
    float (*epi)[16][16]         = ( float(*)[16][16])         (smf + 68608);
    uint32_t sQ = smem_u32(smf) + 34816u;
    uint32_t sK = smem_u32(smf) + 45056u;
    uint32_t sV = smem_u32(smf) + 34816u;

    int split = blockIdx.x, b = blockIdx.y;
    int tok0 = split * TSPL;
    int tid = threadIdx.x;
    int w = tid >> 5, lane = tid & 31;
    int wm = w >> 2, wn = w & 3;

    #define F1_STAGE(kc, bb, col0) {                                               \
        {   int ar = tid >> 2, ac = (tid & 3) * 8;                                 \
            CPA16(sQ + (uint32_t)(bb)*5120u + (uint32_t)ar*80u + (uint32_t)ac*2u,  \
                  g_qap + (size_t)ar*DD + (kc) + ac); }                            \
        _Pragma("unroll")                                                          \
        for (int r = 0; r < 2; r++) {                                              \
            int idx = tid + r*256;                                                 \
            int kr = idx >> 2, kcc = (idx & 3) * 8;                                \
            CPA16(sK + (uint32_t)(bb)*10240u + (uint32_t)kr*80u + (uint32_t)kcc*2u,\
                  g_xb + (size_t)(b*NT + (col0) + kr)*DD + (kc) + kcc);            \
        }                                                                          \
        CPA_COMMIT(); }

    #pragma unroll 1
    for (int t = 0; t < 2; t++) {
        int col0 = tok0 + t*128;
        wmma::fragment<wmma::accumulator,16,16,16,float> acc[2][2];
        #pragma unroll
        for (int i = 0; i < 2; i++)
            #pragma unroll
            for (int j = 0; j < 2; j++) wmma::fill_fragment(acc[i][j], 0.f);

        F1_STAGE(0, 0, col0);
        for (int s = 0; s < 8; s++) {
            CPA_WAIT(0);
            __syncthreads();
            if (s < 7) F1_STAGE((s+1)*32, (s+1)&1, col0);
            int bb = s & 1;
            #pragma unroll
            for (int kk = 0; kk < 2; kk++) {
                wmma::fragment<wmma::matrix_a,16,16,16,__nv_bfloat16,wmma::row_major> af[2];
                wmma::fragment<wmma::matrix_b,16,16,16,__nv_bfloat16,wmma::col_major> bf[2];
                #pragma unroll
                for (int i = 0; i < 2; i++)
                    wmma::load_matrix_sync(af[i], &Qa[bb][wm*32 + i*16][kk*16], 40);
                #pragma unroll
                for (int j = 0; j < 2; j++)
                    wmma::load_matrix_sync(bf[j], &Ks[bb][wn*32 + j*16][kk*16], 40);
                #pragma unroll
                for (int i = 0; i < 2; i++)
                    #pragma unroll
                    for (int j = 0; j < 2; j++)
                        wmma::mma_sync(acc[i][j], af[i], bf[j], acc[i][j]);
            }
        }
        __syncthreads();
        #pragma unroll
        for (int i = 0; i < 2; i++)
            #pragma unroll
            for (int j = 0; j < 2; j++) {
                wmma::store_matrix_sync(&epi[w][0][0], acc[i][j], 16, wmma::mem_row_major);
                __syncwarp();
                if (lane < 16) {
                    int ga = wm*32 + i*16 + lane;
                    int gc = t*128 + wn*32 + j*16;
                    __nv_bfloat16 t8[8];
                    #pragma unroll
                    for (int g = 0; g < 2; g++) {
                        #pragma unroll
                        for (int e = 0; e < 8; e++)
                            t8[e] = __float2bfloat16(epi[w][lane][g*8+e]);
                        *(uint4*)(&L[ga][gc + g*8]) = *(uint4*)t8;
                    }
                }
                __syncwarp();
            }
        __syncthreads();
    }
    #undef F1_STAGE

    // split softmax over 256 cols: row = tid>>2, 4 threads/row
    {
        int row = tid >> 2, q = tid & 3;
        float m = -1e30f;
        #pragma unroll 8
        for (int c = 0; c < 64; c++)
            m = fmaxf(m, __bfloat162float(L[row][q*64 + c]));
        m = fmaxf(m, __shfl_xor_sync(0xffffffffu, m, 1));
        m = fmaxf(m, __shfl_xor_sync(0xffffffffu, m, 2));
        float sum = 0.f;
        #pragma unroll 8
        for (int c = 0; c < 64; c++) {
            float p = __expf(__bfloat162float(L[row][q*64 + c]) - m);
            sum += p;
            L[row][q*64 + c] = __float2bfloat16(p);
        }
        sum += __shfl_xor_sync(0xffffffffu, sum, 1);
        sum += __shfl_xor_sync(0xffffffffu, sum, 2);
        if (q == 0)
            g_stats[(b*SPL + split)*NA + row] = make_float2(m, sum);
    }
    __syncthreads();

    // pass 2: u_split[64,256] = P[64,256] @ x_split[256,256]
    {
        wmma::fragment<wmma::accumulator,16,16,16,float> acc[2][4];
        #pragma unroll
        for (int i = 0; i < 2; i++)
            #pragma unroll
            for (int j = 0; j < 4; j++) wmma::fill_fragment(acc[i][j], 0.f);

        #define F2_STAGE(kc, bb) {                                                 \
            _Pragma("unroll")                                                      \
            for (int r = 0; r < 4; r++) {                                          \
                int idx = tid + r*256;                                             \
                int vr = idx >> 5, vc = (idx & 31) * 8;                            \
                CPA16(sV + (uint32_t)(bb)*16896u + (uint32_t)vr*528u + (uint32_t)vc*2u,\
                      g_xb + (size_t)(b*NT + tok0 + (kc) + vr)*DD + vc);           \
            }                                                                      \
            CPA_COMMIT(); }

        F2_STAGE(0, 0);
        for (int s = 0; s < 8; s++) {
            CPA_WAIT(0);
            __syncthreads();
            if (s < 7) F2_STAGE((s+1)*32, (s+1)&1);
            int bb = s & 1;
            #pragma unroll
            for (int kk = 0; kk < 2; kk++) {
                wmma::fragment<wmma::matrix_a,16,16,16,__nv_bfloat16,wmma::row_major> af[2];
                wmma::fragment<wmma::matrix_b,16,16,16,__nv_bfloat16,wmma::row_major> bf[4];
                #pragma unroll
                for (int i = 0; i < 2; i++)
                    wmma::load_matrix_sync(af[i], &L[wm*32 + i*16][s*32 + kk*16], 272);
                #pragma unroll
                for (int j = 0; j < 4; j++)
                    wmma::load_matrix_sync(bf[j], &Vs[bb][kk*16][wn*64 + j*16], 264);
                #pragma unroll
                for (int i = 0; i < 2; i++)
                    #pragma unroll
                    for (int j = 0; j < 4; j++)
                        wmma::mma_sync(acc[i][j], af[i], bf[j], acc[i][j]);
            }
        }
        #undef F2_STAGE
        __syncthreads();

        float* outb = g_vap + (size_t)(b*SPL + split)*NA*DD;
        #pragma unroll
        for (int i = 0; i < 2; i++)
            #pragma unroll
            for (int j = 0; j < 4; j++) {
                wmma::store_matrix_sync(&epi[w][0][0], acc[i][j], 16, wmma::mem_row_major);
                __syncwarp();
                #pragma unroll
                for (int e = 0; e < 2; e++) {
                    int idx2 = lane + e*32;
                    int r = idx2 >> 2, c4 = (idx2 & 3) * 4;
                    int ga = wm*32 + i*16 + r;
                    int gd = wn*64 + j*16 + c4;
                    *(float4*)(outb + (size_t)ga*DD + gd) = *(float4*)(&epi[w][r][c4]);
                }
                __syncwarp();
            }
    }
}

// ---------------- fc1: combine splits (rescale), then va2 = u @ Wvf2 + bvf2 --
__global__ void fc1k() {
    __shared__ float r0[DD];
    __shared__ float ms[SPL], ss[SPL];
    int row = blockIdx.x;  // b*NA + a
    int b = row >> 6, a = row & 63;
    int i = threadIdx.x;

    if (i < SPL) {
        float2 st = g_stats[(b*SPL + i)*NA + a];
        ms[i] = st.x; ss[i] = st.y;
    }
    __syncthreads();
    float m = -1e30f;
    #pragma unroll
    for (int s = 0; s < SPL; s++) m = fmaxf(m, ms[s]);
    float S = 0.f;
    float wsc[SPL];
    #pragma unroll
    for (int s = 0; s < SPL; s++) {
        wsc[s] = __expf(ms[s] - m);
        S += wsc[s] * ss[s];
    }
    float acc = 0.f;
    #pragma unroll
    for (int s = 0; s < SPL; s++)
        acc += wsc[s] * g_vap[(size_t)(b*SPL + s)*NA*DD + (size_t)a*DD + i];
    r0[i] = acc / S;
    __syncthreads();
    int o = threadIdx.x;
    float sum = g_bvf2[o];
    #pragma unroll 8
    for (int d = 0; d < DD; d++) sum += r0[d] * g_Wvf2[d*DD + o];
    g_va[(size_t)row*DD + o] = __float2bfloat16(sum);
}

// ======== stage 2 (64-token tiles): logits -> softmax -> P@va2 + bfc2 + x ====
// grid (64, 8), 256 threads, dyn smem 71680:
//  Qs 2x[64][40]@0 (10240) | Ka 2x[64][40]@10240 (10240)
//  logits f32 [64][68]@20480 (17408) | Vs [64][264]@37888 (33792)
//  Pm [64][72] reuses Qs | epi reuses Ka
__global__ void __launch_bounds__(256) stage2(const float* __restrict__ bfc2,
                                              const float* __restrict__ x,
                                              float* __restrict__ out) {
    extern __shared__ __align__(16) char sm2[];
    __nv_bfloat16 (*Qs)[64][40] = ( __nv_bfloat16(*)[64][40]) sm2;
    __nv_bfloat16 (*Ka)[64][40] = ( __nv_bfloat16(*)[64][40]) (sm2 + 10240);
    float* logits               = ( float*)                   (sm2 + 20480);
    __nv_bfloat16 (*Vs)[264]    = ( __nv_bfloat16(*)[264])    (sm2 + 37888);
    __nv_bfloat16 (*Pm)[72]     = ( __nv_bfloat16(*)[72])     sm2;
    float (*epi)[16][16]        = ( float(*)[16][16])         (sm2 + 10240);
    __shared__ float dbs[NA];
    uint32_t sQ = smem_u32(sm2), sKa = sQ + 10240u, sV = sQ + 37888u;

    int b = blockIdx.y, t0 = blockIdx.x * 64;
    int tid = threadIdx.x;
    int w = tid >> 5, lane = tid & 31;
    int wm = w >> 2, wn = w & 3;

    if (tid < NA) dbs[tid] = g_dbias[tid];

    // async prefetch va2 tile [64,256] into Vs
    #pragma unroll
    for (int r = 0; r < 8; r++) {
        int idx = tid + r*256;
        int vr = idx >> 5, vc = (idx & 31) * 8;
        CPA16(sV + (uint32_t)vr*528u + (uint32_t)vc*2u,
              g_va + (size_t)(b*NA + vr)*DD + vc);
    }
    CPA_COMMIT();

    // --- phase A: logits[64,64] = x_tile[64,256] @ Ka'[64,256]^T ---
    {
        wmma::fragment<wmma::accumulator,16,16,16,float> acc[2];
        #pragma unroll
        for (int i = 0; i < 2; i++) wmma::fill_fragment(acc[i], 0.f);

        #define S2_STAGE(kc, bb) {                                                 \
            {   int qr = tid >> 2, qc = (tid & 3) * 8;                             \
                CPA16(sQ + (uint32_t)(bb)*5120u + (uint32_t)qr*80u + (uint32_t)qc*2u, \
                      g_xb + (size_t)(b*NT + t0 + qr)*DD + (kc) + qc); }           \
            {   int ar = tid >> 2, ac = (tid & 3) * 8;                             \
                CPA16(sKa + (uint32_t)(bb)*5120u + (uint32_t)ar*80u + (uint32_t)ac*2u, \
                      g_kat + (size_t)ar*DD + (kc) + ac); }                        \
            CPA_COMMIT(); }

        S2_STAGE(0, 0);
        for (int s = 0; s < 8; s++) {
            CPA_WAIT(0);
            __syncthreads();
            if (s < 7) S2_STAGE((s+1)*32, (s+1)&1);
            int bb = s & 1;
            #pragma unroll
            for (int kk = 0; kk < 2; kk++) {
                wmma::fragment<wmma::matrix_a,16,16,16,__nv_bfloat16,wmma::row_major> af[2];
                wmma::fragment<wmma::matrix_b,16,16,16,__nv_bfloat16,wmma::col_major> bf;
                #pragma unroll
                for (int i = 0; i < 2; i++)
                    wmma::load_matrix_sync(af[i], &Qs[bb][wm*32 + i*16][kk*16], 40);
                wmma::load_matrix_sync(bf, &Ka[bb][wn*16][kk*16], 40);
                #pragma unroll
                for (int i = 0; i < 2; i++)
                    wmma::mma_sync(acc[i], af[i], bf, acc[i]);
            }
        }
        #undef S2_STAGE
        __syncthreads();
        #pragma unroll
        for (int i = 0; i < 2; i++)
            wmma::store_matrix_sync(logits + (wm*32 + i*16)*68 + wn*16,
                                    acc[i], 68, wmma::mem_row_major);
    }
    __syncthreads();

    // --- phase B: per-row softmax over 64 agents (+dbias); 4 threads/row ---
    {
        int row = tid >> 2, q = tid & 3;
        const float* lr = logits + row*68 + q*16;
        float lv[16];
        #pragma unroll
        for (int c = 0; c < 16; c++) lv[c] = lr[c] + dbs[q*16 + c];
        float m = -1e30f;
        #pragma unroll
        for (int c = 0; c < 16; c++) m = fmaxf(m, lv[c]);
        m = fmaxf(m, __shfl_xor_sync(0xffffffffu, m, 1));
        m = fmaxf(m, __shfl_xor_sync(0xffffffffu, m, 2));
        float sum = 0.f;
        float pv[16];
        #pragma unroll
        for (int c = 0; c < 16; c++) { pv[c] = __expf(lv[c] - m); sum += pv[c]; }
        sum += __shfl_xor_sync(0xffffffffu, sum, 1);
        sum += __shfl_xor_sync(0xffffffffu, sum, 2);
        float inv = 1.f / sum;
        __syncthreads();   // logits (Qs region unrelated) — ensure all reads of logits done before Pm overwrite of Qs
        #pragma unroll
        for (int c = 0; c < 16; c++)
            Pm[row][q*16 + c] = __float2bfloat16(pv[c] * inv);
    }
    __syncthreads();

    // --- phase C: out[64,256] = Pm[64,64] @ Vs[64,256] + bfc2 + x ---
    {
        wmma::fragment<wmma::accumulator,16,16,16,float> acc[2][4];
        #pragma unroll
        for (int i = 0; i < 2; i++)
            #pragma unroll
            for (int j = 0; j < 4; j++) wmma::fill_fragment(acc[i][j], 0.f);
        #pragma unroll
        for (int kk = 0; kk < 4; kk++) {
            wmma::fragment<wmma::matrix_a,16,16,16,__nv_bfloat16,wmma::row_major> af[2];
            wmma::fragment<wmma::matrix_b,16,16,16,__nv_bfloat16,wmma::row_major> bf[4];
            #pragma unroll
            for (int i = 0; i < 2; i++)
                wmma::load_matrix_sync(af[i], &Pm[wm*32 + i*16][kk*16], 72);
            #pragma unroll
            for (int j = 0; j < 4; j++)
                wmma::load_matrix_sync(bf[j], &Vs[kk*16][wn*64 + j*16], 264);
            #pragma unroll
            for (int i = 0; i < 2; i++)
                #pragma unroll
                for (int j = 0; j < 4; j++)
                    wmma::mma_sync(acc[i][j], af[i], bf[j], acc[i][j]);
        }
        __syncthreads();   // Pm reads done; epi (Ka region) free since phase A
        int r = lane >> 1, c8 = (lane & 1) * 8;
        #pragma unroll
        for (int i = 0; i < 2; i++)
            #pragma unroll
            for (int j = 0; j < 4; j++) {
                wmma::store_matrix_sync(&epi[w][0][0], acc[i][j], 16, wmma::mem_row_major);
                __syncwarp();
                int grow = t0 + wm*32 + i*16 + r;
                int gcol = wn*64 + j*16 + c8;
                size_t gi = (size_t)(b*NT + grow)*DD + gcol;
                float o0[4], o1[4];
                #pragma unroll
                for (int e = 0; e < 4; e++)
                    o0[e] = epi[w][r][c8+e]   + bfc2[gcol+e]   + x[gi+e];
                #pragma unroll
                for (int e = 0; e < 4; e++)
                    o1[e] = epi[w][r][c8+4+e] + bfc2[gcol+4+e] + x[gi+4+e];
                *(float4*)(out + gi)     = *(float4*)o0;
                *(float4*)(out + gi + 4) = *(float4*)o1;
                __syncwarp();
            }
    }
}

// ---------------- launcher ---------------------------------------------------
#define S1F_SMEM 76800
#define S2_SMEM  71680
#define PREP_SMEM 45056

extern "C" void kernel_launch(void* const* d_in, const int* in_sizes, int n_in,
                              void* d_out, int out_size) {
    const float* agent = (const float*)d_in[0];
    const float* x     = (const float*)d_in[1];
    const float* Wqkv  = (const float*)d_in[2];
    const float* bqkv  = (const float*)d_in[3];
    const float* Wag   = (const float*)d_in[4];
    const float* bag   = (const float*)d_in[5];
    const float* Wfc1  = (const float*)d_in[6];
    const float* bfc1  = (const float*)d_in[7];
    const float* Wfc2  = (const float*)d_in[8];
    const float* bfc2  = (const float*)d_in[9];
    float* out = (float*)d_out;

    cudaFuncSetAttribute(s1fused, cudaFuncAttributeMaxDynamicSharedMemorySize, S1F_SMEM);
    cudaFuncSetAttribute(stage2,  cudaFuncAttributeMaxDynamicSharedMemorySize, S2_SMEM);

    prep0<<<1088, 512>>>(x, Wfc2, Wqkv, Wfc1, agent, Wag, bag);
    prep1<<<89, 256, PREP_SMEM>>>(bqkv, Wfc1, bfc1);
    prep2<<<17, 256, PREP_SMEM>>>(Wfc2);
    s1fused<<<dim3(SPL, NB), 256, S1F_SMEM>>>();
    fc1k<<<512, 256>>>();
    stage2<<<dim3(64, 8), 256, S2_SMEM>>>(bfc2, x, out);
}